// round 3
// baseline (speedup 1.0000x reference)
#include <cuda_runtime.h>
#include <math.h>

#define NS 1024

// ---------------- scratch (no allocations allowed) ----------------
__device__ float g_h1p[NS*32*36*16];   // after stage1 pool
__device__ float g_h2p[NS*64*12*4];    // after stage2 pool
__device__ float g_h3p[NS*128*4*2];    // after stage3 pool (== flattened [S,1024])
__device__ float g_e [NS*128];
__device__ float g_q [NS*128];
__device__ float g_k [NS*128];
__device__ float g_v [NS*128];
__device__ float g_ao[NS*128];
__device__ float g_o2[NS*128];
__device__ float g_ea[NS*128];
__device__ float g_sq[NS];
__device__ unsigned int g_dmax;

__device__ __forceinline__ float selu_f(float x) {
    const float a = 1.6732632423543772f, sc = 1.0507009873554805f;
    return x > 0.f ? sc * x : sc * a * (expf(x) - 1.f);
}

// ============ Stage 1: conv(1->32,6x4) + SELU + GN(1ch/grp) + pool(2,4) ============
// grid (1024 frames, 32 channels), 256 threads
__global__ void k_conv1(const float* __restrict__ x, const float* __restrict__ w,
                        const float* __restrict__ bias, const float* __restrict__ gg,
                        const float* __restrict__ gb) {
    int s = blockIdx.x, c = blockIdx.y;
    __shared__ float pad[77*67];
    __shared__ float cv[72*64];
    __shared__ float wt[24];
    __shared__ float rs[8], rq[8];
    int tid = threadIdx.x;
    if (tid < 24) wt[tid] = w[c*24 + tid];
    const float* xs = x + s*4608;
    for (int i = tid; i < 77*67; i += 256) {
        int r = i / 67, cc = i - r*67;
        int ih = r - 2, iw = cc - 1;
        pad[i] = (ih >= 0 && ih < 72 && iw >= 0 && iw < 64) ? xs[ih*64 + iw] : 0.f;
    }
    __syncthreads();
    float bsum = 0.f, bsq = 0.f;
    float bi = bias[c];
    for (int p = tid; p < 4608; p += 256) {
        int oh = p >> 6, ow = p & 63;
        float acc = bi;
        #pragma unroll
        for (int kh = 0; kh < 6; kh++) {
            const float* pr = &pad[(oh+kh)*67 + ow];
            #pragma unroll
            for (int kw = 0; kw < 4; kw++) acc += pr[kw] * wt[kh*4 + kw];
        }
        acc = selu_f(acc);
        cv[p] = acc;
        bsum += acc; bsq += acc*acc;
    }
    #pragma unroll
    for (int o = 16; o; o >>= 1) {
        bsum += __shfl_down_sync(0xffffffffu, bsum, o);
        bsq  += __shfl_down_sync(0xffffffffu, bsq , o);
    }
    if ((tid & 31) == 0) { rs[tid>>5] = bsum; rq[tid>>5] = bsq; }
    __syncthreads();
    if (tid == 0) {
        float a = 0.f, b = 0.f;
        for (int i = 0; i < 8; i++) { a += rs[i]; b += rq[i]; }
        rs[0] = a; rq[0] = b;
    }
    __syncthreads();
    float mean = rs[0] * (1.f/4608.f);
    float var  = rq[0] * (1.f/4608.f) - mean*mean;
    float sc = gg[c] * rsqrtf(var + 1e-5f);
    float sh = gb[c] - mean * sc;
    for (int q = tid; q < 576; q += 256) {
        int ph = q >> 4, pw = q & 15;
        float m = -INFINITY;
        #pragma unroll
        for (int kh = 0; kh < 2; kh++)
            #pragma unroll
            for (int kw = 0; kw < 4; kw++)
                m = fmaxf(m, cv[(2*ph+kh)*64 + 4*pw+kw]*sc + sh);
        g_h1p[((s*32 + c)*36 + ph)*16 + pw] = m;
    }
}

// ============ Stage 2: conv(32->64,6x4) + SELU + GN(2ch/grp) + pool(3,4) ============
// grid (1024 frames, 32 groups), 192 threads, dyn smem = (24928+1152+1536)*4
__global__ void k_conv2(const float* __restrict__ w, const float* __restrict__ bias,
                        const float* __restrict__ gg, const float* __restrict__ gb) {
    extern __shared__ float sm2[];
    float* pad = sm2;               // 32*779
    float* cv  = sm2 + 24928;       // 2*576
    float* ws  = sm2 + 24928+1152;  // 2*32*24
    __shared__ float rs[6], rq[6];
    int s = blockIdx.x, g = blockIdx.y;
    int c0 = 2*g;
    int tid = threadIdx.x;  // 192
    for (int i = tid; i < 1536; i += 192) ws[i] = w[c0*768 + i];
    for (int i = tid; i < 32*779; i += 192) {
        int ch = i / 779; int rem = i - ch*779;
        int r = rem / 19, cc = rem - r*19;
        int ih = r - 2, iw = cc - 1;
        pad[i] = (ih >= 0 && ih < 36 && iw >= 0 && iw < 16)
               ? g_h1p[((s*32 + ch)*36 + ih)*16 + iw] : 0.f;
    }
    __syncthreads();
    float b0v = bias[c0], b1v = bias[c0+1];
    float a0[3] = {b0v, b0v, b0v};
    float a1[3] = {b1v, b1v, b1v};
    int offs[3];
    #pragma unroll
    for (int ii = 0; ii < 3; ii++) {
        int p = tid + 192*ii;
        int oh = p >> 4, ow = p & 15;
        offs[ii] = oh*19 + ow;
    }
    for (int ic = 0; ic < 32; ic++) {
        const float* pch = pad + ic*779;
        const float* w0 = ws + ic*24;
        const float* w1 = ws + 768 + ic*24;
        #pragma unroll
        for (int kh = 0; kh < 6; kh++) {
            float wa0 = w0[kh*4+0], wa1 = w0[kh*4+1], wa2 = w0[kh*4+2], wa3 = w0[kh*4+3];
            float wb0 = w1[kh*4+0], wb1 = w1[kh*4+1], wb2 = w1[kh*4+2], wb3 = w1[kh*4+3];
            #pragma unroll
            for (int ii = 0; ii < 3; ii++) {
                const float* pr = pch + offs[ii] + kh*19;
                float v0 = pr[0], v1 = pr[1], v2 = pr[2], v3 = pr[3];
                a0[ii] += v0*wa0 + v1*wa1 + v2*wa2 + v3*wa3;
                a1[ii] += v0*wb0 + v1*wb1 + v2*wb2 + v3*wb3;
            }
        }
    }
    float bsum = 0.f, bsq = 0.f;
    #pragma unroll
    for (int ii = 0; ii < 3; ii++) {
        int p = tid + 192*ii;
        float u0 = selu_f(a0[ii]), u1 = selu_f(a1[ii]);
        cv[p] = u0; cv[576 + p] = u1;
        bsum += u0 + u1; bsq += u0*u0 + u1*u1;
    }
    #pragma unroll
    for (int o = 16; o; o >>= 1) {
        bsum += __shfl_down_sync(0xffffffffu, bsum, o);
        bsq  += __shfl_down_sync(0xffffffffu, bsq , o);
    }
    if ((tid & 31) == 0) { rs[tid>>5] = bsum; rq[tid>>5] = bsq; }
    __syncthreads();
    if (tid == 0) {
        float a = 0.f, b = 0.f;
        for (int i = 0; i < 6; i++) { a += rs[i]; b += rq[i]; }
        rs[0] = a; rq[0] = b;
    }
    __syncthreads();
    float mean = rs[0] * (1.f/1152.f);
    float var  = rq[0] * (1.f/1152.f) - mean*mean;
    float inv  = rsqrtf(var + 1e-5f);
    if (tid < 96) {
        int ch = tid / 48; int rem = tid - ch*48;
        int ph = rem >> 2, pw = rem & 3;
        int c = c0 + ch;
        float sc = gg[c] * inv;
        float sh = gb[c] - mean * sc;
        float m = -INFINITY;
        #pragma unroll
        for (int kh = 0; kh < 3; kh++)
            #pragma unroll
            for (int kw = 0; kw < 4; kw++)
                m = fmaxf(m, cv[ch*576 + (3*ph+kh)*16 + 4*pw+kw]*sc + sh);
        g_h2p[((s*64 + c)*12 + ph)*4 + pw] = m;
    }
}

// ============ Stage 3: conv(64->128,6x4) + SELU + GN(4ch/grp) + pool(3,2) ============
// grid (1024 frames, 32 groups), 192 threads, dyn smem = (7616+192+6148)*4
__global__ void k_conv3(const float* __restrict__ w, const float* __restrict__ bias,
                        const float* __restrict__ gg, const float* __restrict__ gb) {
    extern __shared__ float sm3[];
    float* pad = sm3;               // 64*119 = 7616
    float* cv  = sm3 + 7616;        // 4*48
    float* ws  = sm3 + 7616 + 192;  // 4*1537 (padded rows)
    __shared__ float rs[6], rq[6];
    __shared__ float scs[4], shs[4];
    int s = blockIdx.x, g = blockIdx.y;
    int c0 = 4*g;
    int tid = threadIdx.x;  // 192
    for (int i = tid; i < 6144; i += 192) {
        int ch = i / 1536; int rem = i - ch*1536;
        ws[ch*1537 + rem] = w[c0*1536 + i];
    }
    for (int i = tid; i < 64*119; i += 192) {
        int ch = i / 119; int rem = i - ch*119;
        int r = rem / 7, cc = rem - r*7;
        int ih = r - 2, iw = cc - 1;
        pad[i] = (ih >= 0 && ih < 12 && iw >= 0 && iw < 4)
               ? g_h2p[((s*64 + ch)*12 + ih)*4 + iw] : 0.f;
    }
    __syncthreads();
    int pos = tid >> 2, ch = tid & 3;   // 48 positions x 4 channels
    int oh = pos >> 2, ow = pos & 3;
    float acc = bias[c0 + ch];
    const float* wch = ws + ch*1537;
    for (int ic = 0; ic < 64; ic++) {
        const float* pch = pad + ic*119 + oh*7 + ow;
        const float* wc = wch + ic*24;
        #pragma unroll
        for (int kh = 0; kh < 6; kh++)
            #pragma unroll
            for (int kw = 0; kw < 4; kw++)
                acc += pch[kh*7 + kw] * wc[kh*4 + kw];
    }
    acc = selu_f(acc);
    cv[ch*48 + pos] = acc;
    float bsum = acc, bsq = acc*acc;
    #pragma unroll
    for (int o = 16; o; o >>= 1) {
        bsum += __shfl_down_sync(0xffffffffu, bsum, o);
        bsq  += __shfl_down_sync(0xffffffffu, bsq , o);
    }
    if ((tid & 31) == 0) { rs[tid>>5] = bsum; rq[tid>>5] = bsq; }
    __syncthreads();
    if (tid == 0) {
        float a = 0.f, b = 0.f;
        for (int i = 0; i < 6; i++) { a += rs[i]; b += rq[i]; }
        rs[0] = a; rq[0] = b;
    }
    __syncthreads();
    float mean = rs[0] * (1.f/192.f);
    float var  = rq[0] * (1.f/192.f) - mean*mean;
    float inv  = rsqrtf(var + 1e-5f);
    if (tid < 4) {
        int c = c0 + tid;
        float sc = gg[c] * inv;
        scs[tid] = sc;
        shs[tid] = gb[c] - mean * sc;
    }
    __syncthreads();
    if (tid < 32) {
        int pch = tid >> 3; int rem = tid & 7;
        int ph = rem >> 1, pw = rem & 1;
        float sc = scs[pch], sh = shs[pch];
        float m = -INFINITY;
        #pragma unroll
        for (int kh = 0; kh < 3; kh++)
            #pragma unroll
            for (int kw = 0; kw < 2; kw++)
                m = fmaxf(m, cv[pch*48 + (3*ph+kh)*4 + 2*pw+kw]*sc + sh);
        g_h3p[((s*128 + c0 + pch)*4 + ph)*2 + pw] = m;
    }
}

// ============ FC: e = l2norm_row( selu( h3 @ W^T + b ) ) ============
// grid 1024, 128 threads
__global__ void k_fc(const float* __restrict__ w, const float* __restrict__ bias) {
    __shared__ float xr[1024];
    __shared__ float wt[128*65];   // padded stride 65
    __shared__ float rs[4];
    int s = blockIdx.x, tid = threadIdx.x;
    for (int i = tid; i < 1024; i += 128) xr[i] = g_h3p[s*1024 + i];
    float acc = bias[tid];
    for (int k0 = 0; k0 < 1024; k0 += 64) {
        __syncthreads();
        for (int i = tid; i < 8192; i += 128) {
            int j = i >> 6, kk = i & 63;
            wt[j*65 + kk] = w[j*1024 + k0 + kk];
        }
        __syncthreads();
        const float* wr = wt + tid*65;
        const float* xk = xr + k0;
        #pragma unroll
        for (int kk = 0; kk < 64; kk++) acc += xk[kk] * wr[kk];
    }
    acc = selu_f(acc);
    float ss = acc*acc;
    #pragma unroll
    for (int o = 16; o; o >>= 1) ss += __shfl_down_sync(0xffffffffu, ss, o);
    if ((tid & 31) == 0) rs[tid>>5] = ss;
    __syncthreads();
    float tot = rs[0] + rs[1] + rs[2] + rs[3];
    float n = fmaxf(sqrtf(tot), 1e-12f);
    g_e[s*128 + tid] = acc / n;
}

// ============ QKV + SELU, PE added to K ============
// grid 1024, 128 threads, dyn smem = 128*129*4
__global__ void k_qkv(const float* __restrict__ wq, const float* __restrict__ bq,
                      const float* __restrict__ wk, const float* __restrict__ bk,
                      const float* __restrict__ wv, const float* __restrict__ bv) {
    extern __shared__ float wt[];     // 128*129 padded
    __shared__ float er[128];
    int s = blockIdx.x, tid = threadIdx.x;
    er[tid] = g_e[s*128 + tid];
    // Q
    __syncthreads();
    for (int i = tid; i < 16384; i += 128) { int j = i >> 7, d = i & 127; wt[j*129 + d] = wq[i]; }
    __syncthreads();
    {
        float acc = bq[tid];
        const float* wr = wt + tid*129;
        #pragma unroll 8
        for (int d = 0; d < 128; d++) acc += er[d] * wr[d];
        g_q[s*128 + tid] = selu_f(acc);
    }
    // K (+PE)
    __syncthreads();
    for (int i = tid; i < 16384; i += 128) { int j = i >> 7, d = i & 127; wt[j*129 + d] = wk[i]; }
    __syncthreads();
    {
        float acc = bk[tid];
        const float* wr = wt + tid*129;
        #pragma unroll 8
        for (int d = 0; d < 128; d++) acc += er[d] * wr[d];
        acc = selu_f(acc);
        float t = (float)(tid & ~1);
        float f = expf(t * (-9.210340371976184f / 128.f));
        float ang = (float)s * f;
        acc += (tid & 1) ? cosf(ang) : sinf(ang);
        g_k[s*128 + tid] = acc;
    }
    // V
    __syncthreads();
    for (int i = tid; i < 16384; i += 128) { int j = i >> 7, d = i & 127; wt[j*129 + d] = wv[i]; }
    __syncthreads();
    {
        float acc = bv[tid];
        const float* wr = wt + tid*129;
        #pragma unroll 8
        for (int d = 0; d < 128; d++) acc += er[d] * wr[d];
        g_v[s*128 + tid] = selu_f(acc);
    }
}

// ============ attention: softmax(qK^T/sqrt(128)) @ V, fused per row ============
// grid 1024, 256 threads
__global__ void k_attn() {
    __shared__ __align__(16) float qr[128];
    __shared__ float p[1024];
    __shared__ float rs[8];
    __shared__ float part[128];
    int s = blockIdx.x, tid = threadIdx.x;
    if (tid < 128) qr[tid] = g_q[s*128 + tid];
    __syncthreads();
    const float scale = 0.08838834764831845f;  // 1/sqrt(128)
    float lmax = -INFINITY;
    for (int t = tid; t < 1024; t += 256) {
        const float4* kr = (const float4*)(g_k + t*128);
        const float4* q4 = (const float4*)qr;
        float acc = 0.f;
        #pragma unroll
        for (int d4 = 0; d4 < 32; d4++) {
            float4 kv = kr[d4];
            float4 qv = q4[d4];
            acc += qv.x*kv.x + qv.y*kv.y + qv.z*kv.z + qv.w*kv.w;
        }
        acc *= scale;
        p[t] = acc;
        lmax = fmaxf(lmax, acc);
    }
    #pragma unroll
    for (int o = 16; o; o >>= 1) lmax = fmaxf(lmax, __shfl_down_sync(0xffffffffu, lmax, o));
    if ((tid & 31) == 0) rs[tid>>5] = lmax;
    __syncthreads();
    float m = -INFINITY;
    for (int i = 0; i < 8; i++) m = fmaxf(m, rs[i]);
    float lsum = 0.f;
    for (int t = tid; t < 1024; t += 256) {
        float ev = expf(p[t] - m);
        p[t] = ev;
        lsum += ev;
    }
    __syncthreads();
    #pragma unroll
    for (int o = 16; o; o >>= 1) lsum += __shfl_down_sync(0xffffffffu, lsum, o);
    if ((tid & 31) == 0) rs[tid>>5] = lsum;
    __syncthreads();
    float tot = 0.f;
    for (int i = 0; i < 8; i++) tot += rs[i];
    float inv = 1.f / tot;
    // attn @ V : 256 threads = 128 cols x 2 halves of t-range
    int d = tid & 127, half = tid >> 7;
    float acc = 0.f;
    int t0 = half * 512;
    for (int t = t0; t < t0 + 512; t++) acc += p[t] * g_v[t*128 + d];
    if (half == 1) part[d] = acc;
    __syncthreads();
    if (half == 0) g_ao[s*128 + d] = (acc + part[d]) * inv;
}

// ============ column-wise l2norms: out = l2norm_col(ao)+e ; ea = l2norm_col(out) ============
// grid 1, 128 threads (one per column)
__global__ void k_colfix() {
    int d = threadIdx.x;
    float ss = 0.f;
    for (int s = 0; s < 1024; s++) { float v = g_ao[s*128 + d]; ss += v*v; }
    float inv1 = 1.f / fmaxf(sqrtf(ss), 1e-12f);
    float ss2 = 0.f;
    for (int s = 0; s < 1024; s++) {
        float v = g_ao[s*128 + d]*inv1 + g_e[s*128 + d];
        g_o2[s*128 + d] = v;
        ss2 += v*v;
    }
    float inv2 = 1.f / fmaxf(sqrtf(ss2), 1e-12f);
    for (int s = 0; s < 1024; s++) g_ea[s*128 + d] = g_o2[s*128 + d] * inv2;
}

// row sum-of-squares of ea
__global__ void k_rowsq() {
    int s = blockIdx.x*128 + threadIdx.x;
    const float4* r = (const float4*)(g_ea + s*128);
    float ss = 0.f;
    #pragma unroll
    for (int i = 0; i < 32; i++) {
        float4 v = r[i];
        ss += v.x*v.x + v.y*v.y + v.z*v.z + v.w*v.w;
    }
    g_sq[s] = ss;
}

__global__ void k_init() { g_dmax = 0u; }

// ============ pairwise distances d into d_out + global max ============
// grid (32,32), 256 threads (16x16), each thread computes a 2x2 microtile
__global__ void k_gram(float* __restrict__ dout) {
    __shared__ float ea_i[32][129];
    __shared__ float ea_j[32][129];
    __shared__ float sqi[32], sqj[32];
    __shared__ float rmax[8];
    int i0 = blockIdx.y * 32, j0 = blockIdx.x * 32;
    int tid = threadIdx.x;
    for (int idx = tid; idx < 4096; idx += 256) {
        int r = idx >> 7, d = idx & 127;
        ea_i[r][d] = g_ea[(i0+r)*128 + d];
        ea_j[r][d] = g_ea[(j0+r)*128 + d];
    }
    if (tid < 32) { sqi[tid] = g_sq[i0 + tid]; sqj[tid] = g_sq[j0 + tid]; }
    __syncthreads();
    int tx = tid & 15, ty = tid >> 4;
    int r0 = 2*ty, c0 = 2*tx;
    float d00 = 0.f, d01 = 0.f, d10 = 0.f, d11 = 0.f;
    #pragma unroll 4
    for (int d = 0; d < 128; d++) {
        float a0 = ea_i[r0][d], a1 = ea_i[r0+1][d];
        float b0 = ea_j[c0][d], b1 = ea_j[c0+1][d];
        d00 += a0*b0; d01 += a0*b1; d10 += a1*b0; d11 += a1*b1;
    }
    float lm = 0.f;
    float dots[4] = {d00, d01, d10, d11};
    #pragma unroll
    for (int u = 0; u < 4; u++) {
        int r = r0 + (u >> 1), c = c0 + (u & 1);
        float d2 = fmaxf(sqi[r] + sqj[c] - 2.f*dots[u], 0.f);
        float dd = sqrtf(d2 + 1e-12f);
        dout[(i0+r)*1024 + j0 + c] = dd;
        lm = fmaxf(lm, dd);
    }
    #pragma unroll
    for (int o = 16; o; o >>= 1) lm = fmaxf(lm, __shfl_down_sync(0xffffffffu, lm, o));
    if ((tid & 31) == 0) rmax[tid>>5] = lm;
    __syncthreads();
    if (tid == 0) {
        float m = 0.f;
        for (int i = 0; i < 8; i++) m = fmaxf(m, rmax[i]);
        atomicMax(&g_dmax, __float_as_uint(m));  // valid: all values >= 0
    }
}

__global__ void k_final(float* __restrict__ dout) {
    float inv = 1.f / __uint_as_float(g_dmax);
    int i = blockIdx.x*256 + threadIdx.x;
    dout[i] = 1.f - dout[i]*inv;
}

// ---------------- launcher ----------------
extern "C" void kernel_launch(void* const* d_in, const int* in_sizes, int n_in,
                              void* d_out, int out_size) {
    const float* x    = (const float*)d_in[0];
    const float* c1w  = (const float*)d_in[1];
    const float* c1b  = (const float*)d_in[2];
    const float* g1g  = (const float*)d_in[3];
    const float* g1b  = (const float*)d_in[4];
    const float* c2w  = (const float*)d_in[5];
    const float* c2b  = (const float*)d_in[6];
    const float* g2g  = (const float*)d_in[7];
    const float* g2b  = (const float*)d_in[8];
    const float* c3w  = (const float*)d_in[9];
    const float* c3b  = (const float*)d_in[10];
    const float* g3g  = (const float*)d_in[11];
    const float* g3b  = (const float*)d_in[12];
    const float* fcw  = (const float*)d_in[13];
    const float* fcb  = (const float*)d_in[14];
    const float* wq   = (const float*)d_in[15];
    const float* bq   = (const float*)d_in[16];
    const float* wk   = (const float*)d_in[17];
    const float* bk   = (const float*)d_in[18];
    const float* wv   = (const float*)d_in[19];
    const float* bv   = (const float*)d_in[20];
    float* out = (float*)d_out;

    cudaFuncSetAttribute(k_conv2, cudaFuncAttributeMaxDynamicSharedMemorySize, (24928+1152+1536)*4);
    cudaFuncSetAttribute(k_conv3, cudaFuncAttributeMaxDynamicSharedMemorySize, (7616+192+6148)*4);
    cudaFuncSetAttribute(k_qkv,   cudaFuncAttributeMaxDynamicSharedMemorySize, 128*129*4);

    k_conv1<<<dim3(1024,32), 256>>>(x, c1w, c1b, g1g, g1b);
    k_conv2<<<dim3(1024,32), 192, (24928+1152+1536)*4>>>(c2w, c2b, g2g, g2b);
    k_conv3<<<dim3(1024,32), 192, (7616+192+6148)*4>>>(c3w, c3b, g3g, g3b);
    k_fc  <<<1024, 128>>>(fcw, fcb);
    k_qkv <<<1024, 128, 128*129*4>>>(wq, bq, wk, bk, wv, bv);
    k_attn<<<1024, 256>>>();
    k_colfix<<<1, 128>>>();
    k_rowsq<<<8, 128>>>();
    k_init<<<1, 1>>>();
    k_gram<<<dim3(32,32), 256>>>(out);
    k_final<<<4096, 256>>>(out);
}

// round 4
// speedup vs baseline: 3.5000x; 3.5000x over previous
#include <cuda_runtime.h>
#include <math.h>

#define NS 1024

__device__ float g_h1p[NS*32*36*16];
__device__ float g_h2p[NS*64*12*4];
__device__ float g_h3p[NS*128*4*2];
__device__ float g_e [NS*128];
__device__ float g_q [NS*128];
__device__ float g_k [NS*128];
__device__ float g_v [NS*128];
__device__ float g_ao[NS*128];
__device__ float g_o2[NS*128];
__device__ float g_ea[NS*128];
__device__ float g_sq[NS];
__device__ unsigned int g_dmax;

__device__ __forceinline__ float selu_f(float x) {
    const float a = 1.6732632423543772f, sc = 1.0507009873554805f;
    return x > 0.f ? sc * x : sc * a * (expf(x) - 1.f);
}

__device__ __forceinline__ float2 ffma2(float2 a, float2 b, float2 c) {
    unsigned long long ua = *(unsigned long long*)&a;
    unsigned long long ub = *(unsigned long long*)&b;
    unsigned long long uc = *(unsigned long long*)&c;
    unsigned long long ud;
    asm("fma.rn.f32x2 %0, %1, %2, %3;" : "=l"(ud) : "l"(ua), "l"(ub), "l"(uc));
    return *(float2*)&ud;
}

// ===== conv1: 1 block/frame, 32 ch, pool-minmax fused =====
__global__ void __launch_bounds__(256) k_conv1(const float* __restrict__ x,
        const float* __restrict__ w, const float* __restrict__ bias,
        const float* __restrict__ gg, const float* __restrict__ gb) {
    __shared__ float pad[77*67];
    int s = blockIdx.x, tid = threadIdx.x, lane = tid & 31;
    const float* xs = x + s*4608;
    for (int i = tid; i < 77*67; i += 256) {
        int r = i/67, cc = i - r*67;
        int ih = r-2, iw = cc-1;
        pad[i] = (ih>=0 && ih<72 && iw>=0 && iw<64) ? xs[ih*64+iw] : 0.f;
    }
    __syncthreads();
    for (int cc4 = 0; cc4 < 4; cc4++) {
        int ch = cc4*8 + (tid>>5);
        float2 w2[24];
        #pragma unroll
        for (int k2 = 0; k2 < 24; k2++) { float wv = w[ch*24+k2]; w2[k2] = make_float2(wv, wv); }
        float bi = bias[ch];
        float pm[18], pn[18], sum = 0.f, sq = 0.f;
        for (int wi = 0; wi < 18; wi++) {
            int wdw = wi*32 + lane;
            int ph = wdw>>4, pw = wdw&15;
            float2 acc[2][2];
            #pragma unroll
            for (int r = 0; r < 2; r++)
                #pragma unroll
                for (int cp = 0; cp < 2; cp++) acc[r][cp] = make_float2(bi, bi);
            #pragma unroll
            for (int ir = 0; ir < 7; ir++) {
                const float* pr = &pad[(2*ph+ir)*67 + 4*pw];
                float v[7];
                #pragma unroll
                for (int j = 0; j < 7; j++) v[j] = pr[j];
                #pragma unroll
                for (int r = 0; r < 2; r++) {
                    int kh = ir - r;
                    if (kh >= 0 && kh < 6) {
                        #pragma unroll
                        for (int kw = 0; kw < 4; kw++) {
                            float2 wv = w2[kh*4+kw];
                            #pragma unroll
                            for (int cp = 0; cp < 2; cp++)
                                acc[r][cp] = ffma2(make_float2(v[2*cp+kw], v[2*cp+kw+1]), wv, acc[r][cp]);
                        }
                    }
                }
            }
            float mx = -1e30f, mn = 1e30f;
            #pragma unroll
            for (int r = 0; r < 2; r++)
                #pragma unroll
                for (int cp = 0; cp < 2; cp++) {
                    float u0 = selu_f(acc[r][cp].x), u1 = selu_f(acc[r][cp].y);
                    sum += u0+u1; sq += u0*u0+u1*u1;
                    mx = fmaxf(mx, fmaxf(u0,u1)); mn = fminf(mn, fminf(u0,u1));
                }
            pm[wi] = mx; pn[wi] = mn;
        }
        #pragma unroll
        for (int o = 16; o; o >>= 1) {
            sum += __shfl_xor_sync(0xffffffffu, sum, o);
            sq  += __shfl_xor_sync(0xffffffffu, sq , o);
        }
        float mean = sum*(1.f/4608.f);
        float var  = sq*(1.f/4608.f) - mean*mean;
        float sc = gg[ch]*rsqrtf(var+1e-5f);
        float sh = gb[ch] - mean*sc;
        for (int wi = 0; wi < 18; wi++) {
            int wdw = wi*32 + lane;
            int ph = wdw>>4, pw = wdw&15;
            g_h1p[((s*32+ch)*36+ph)*16+pw] = sc>0.f ? pm[wi]*sc+sh : pn[wi]*sc+sh;
        }
    }
}

// ===== conv2: 16 oc/block, grid (1024,4), 192 thr =====
__global__ void __launch_bounds__(192) k_conv2(const float* __restrict__ w,
        const float* __restrict__ bias, const float* __restrict__ gg,
        const float* __restrict__ gb) {
    __shared__ float pad[6232];
    __shared__ __align__(16) float ws[192*20];
    __shared__ float4 red[192];
    __shared__ float gnsc[16], gnsh[16];
    int s = blockIdx.x, ocb = 16*blockIdx.y, tid = threadIdx.x;
    int quad = tid/48, wdw = tid - quad*48;
    int ph = wdw>>2, pw = wdw&3;
    float2 acc[3][4][2];
    #pragma unroll
    for (int p = 0; p < 2; p++) {
        float2 b2 = make_float2(bias[ocb+quad*4+2*p], bias[ocb+quad*4+2*p+1]);
        #pragma unroll
        for (int r = 0; r < 3; r++)
            #pragma unroll
            for (int c = 0; c < 4; c++) acc[r][c][p] = b2;
    }
    for (int ck = 0; ck < 4; ck++) {
        int ic0 = 8*ck;
        __syncthreads();
        for (int i = tid; i < 3072; i += 192) {
            int oc = i/192, r = i - oc*192;
            ws[r*20+oc] = w[(ocb+oc)*768 + ic0*24 + r];
        }
        for (int i = tid; i < 6232; i += 192) {
            int icl = i/779, rem = i - icl*779;
            int rr = rem/19, cc = rem - rr*19;
            int ih = rr-2, iw = cc-1;
            pad[i] = (ih>=0 && ih<36 && iw>=0 && iw<16)
                   ? g_h1p[((s*32+ic0+icl)*36+ih)*16+iw] : 0.f;
        }
        __syncthreads();
        #pragma unroll 1
        for (int icl = 0; icl < 8; icl++) {
            const float* pb = pad + icl*779;
            #pragma unroll
            for (int kh = 0; kh < 6; kh++) {
                float4 wv[4];
                #pragma unroll
                for (int kw = 0; kw < 4; kw++)
                    wv[kw] = *(const float4*)&ws[(icl*24+kh*4+kw)*20 + 4*quad];
                #pragma unroll
                for (int r = 0; r < 3; r++) {
                    const float* pr = pb + (3*ph+r+kh)*19 + 4*pw;
                    float v[7];
                    #pragma unroll
                    for (int j = 0; j < 7; j++) v[j] = pr[j];
                    #pragma unroll
                    for (int c = 0; c < 4; c++)
                        #pragma unroll
                        for (int kw = 0; kw < 4; kw++) {
                            float2 t = make_float2(v[c+kw], v[c+kw]);
                            acc[r][c][0] = ffma2(t, make_float2(wv[kw].x, wv[kw].y), acc[r][c][0]);
                            acc[r][c][1] = ffma2(t, make_float2(wv[kw].z, wv[kw].w), acc[r][c][1]);
                        }
                }
            }
        }
    }
    float s01 = 0.f, q01 = 0.f, s23 = 0.f, q23 = 0.f;
    float mx[4] = {-1e30f,-1e30f,-1e30f,-1e30f};
    float mn[4] = { 1e30f, 1e30f, 1e30f, 1e30f};
    #pragma unroll
    for (int r = 0; r < 3; r++)
        #pragma unroll
        for (int c = 0; c < 4; c++) {
            float u0 = selu_f(acc[r][c][0].x), u1 = selu_f(acc[r][c][0].y);
            float u2 = selu_f(acc[r][c][1].x), u3 = selu_f(acc[r][c][1].y);
            s01 += u0+u1; q01 += u0*u0+u1*u1;
            s23 += u2+u3; q23 += u2*u2+u3*u3;
            mx[0]=fmaxf(mx[0],u0); mn[0]=fminf(mn[0],u0);
            mx[1]=fmaxf(mx[1],u1); mn[1]=fminf(mn[1],u1);
            mx[2]=fmaxf(mx[2],u2); mn[2]=fminf(mn[2],u2);
            mx[3]=fmaxf(mx[3],u3); mn[3]=fminf(mn[3],u3);
        }
    red[tid] = make_float4(s01, q01, s23, q23);
    __syncthreads();
    if (tid < 8) {
        int qd = tid>>1;
        float sm = 0.f, sv = 0.f;
        for (int j = 0; j < 48; j++) {
            float4 f = red[qd*48+j];
            if (tid & 1) { sm += f.z; sv += f.w; } else { sm += f.x; sv += f.y; }
        }
        float mean = sm*(1.f/1152.f);
        float var  = sv*(1.f/1152.f) - mean*mean;
        float inv  = rsqrtf(var+1e-5f);
        for (int j = 0; j < 2; j++) {
            int lc = 2*tid + j;
            float scv = gg[ocb+lc]*inv;
            gnsc[lc] = scv; gnsh[lc] = gb[ocb+lc] - mean*scv;
        }
    }
    __syncthreads();
    #pragma unroll
    for (int p = 0; p < 2; p++)
        #pragma unroll
        for (int e = 0; e < 2; e++) {
            int lc = quad*4 + 2*p + e, mi = 2*p + e;
            float scv = gnsc[lc], shv = gnsh[lc];
            g_h2p[((s*64+ocb+lc)*12+ph)*4+pw] = scv>0.f ? mx[mi]*scv+shv : mn[mi]*scv+shv;
        }
}

// ===== conv3: 1 block/frame, 128 oc, 256 thr, dyn smem 50688 =====
__global__ void __launch_bounds__(256) k_conv3(const float* __restrict__ w,
        const float* __restrict__ bias, const float* __restrict__ gg,
        const float* __restrict__ gb) {
    extern __shared__ float ws[];   // 96*132
    __shared__ float pad[476];
    int s = blockIdx.x, tid = threadIdx.x;
    int quad = tid>>3, wdw = tid&7;
    int ph = wdw>>1, pw = wdw&1;
    float2 acc[3][2][2];
    #pragma unroll
    for (int p = 0; p < 2; p++) {
        float2 b2 = make_float2(bias[quad*4+2*p], bias[quad*4+2*p+1]);
        #pragma unroll
        for (int r = 0; r < 3; r++)
            #pragma unroll
            for (int c = 0; c < 2; c++) acc[r][c][p] = b2;
    }
    for (int ck = 0; ck < 16; ck++) {
        int ic0 = 4*ck;
        __syncthreads();
        for (int i = tid; i < 12288; i += 256) {
            int oc = i/96, r = i - oc*96;
            ws[r*132+oc] = w[oc*1536 + ic0*24 + r];
        }
        for (int i = tid; i < 476; i += 256) {
            int icl = i/119, rem = i - icl*119;
            int rr = rem/7, cc = rem - rr*7;
            int ih = rr-2, iw = cc-1;
            pad[i] = (ih>=0 && ih<12 && iw>=0 && iw<4)
                   ? g_h2p[((s*64+ic0+icl)*12+ih)*4+iw] : 0.f;
        }
        __syncthreads();
        #pragma unroll 1
        for (int icl = 0; icl < 4; icl++) {
            const float* pb = pad + icl*119;
            #pragma unroll
            for (int kh = 0; kh < 6; kh++) {
                float4 wv[4];
                #pragma unroll
                for (int kw = 0; kw < 4; kw++)
                    wv[kw] = *(const float4*)&ws[(icl*24+kh*4+kw)*132 + 4*quad];
                #pragma unroll
                for (int r = 0; r < 3; r++) {
                    const float* pr = pb + (3*ph+r+kh)*7 + 2*pw;
                    float v[5];
                    #pragma unroll
                    for (int j = 0; j < 5; j++) v[j] = pr[j];
                    #pragma unroll
                    for (int c = 0; c < 2; c++)
                        #pragma unroll
                        for (int kw = 0; kw < 4; kw++) {
                            float2 t = make_float2(v[c+kw], v[c+kw]);
                            acc[r][c][0] = ffma2(t, make_float2(wv[kw].x, wv[kw].y), acc[r][c][0]);
                            acc[r][c][1] = ffma2(t, make_float2(wv[kw].z, wv[kw].w), acc[r][c][1]);
                        }
                }
            }
        }
    }
    float sum = 0.f, sq = 0.f;
    float mx[4] = {-1e30f,-1e30f,-1e30f,-1e30f};
    float mn[4] = { 1e30f, 1e30f, 1e30f, 1e30f};
    #pragma unroll
    for (int r = 0; r < 3; r++)
        #pragma unroll
        for (int c = 0; c < 2; c++) {
            float u0 = selu_f(acc[r][c][0].x), u1 = selu_f(acc[r][c][0].y);
            float u2 = selu_f(acc[r][c][1].x), u3 = selu_f(acc[r][c][1].y);
            sum += u0+u1+u2+u3; sq += u0*u0+u1*u1+u2*u2+u3*u3;
            mx[0]=fmaxf(mx[0],u0); mn[0]=fminf(mn[0],u0);
            mx[1]=fmaxf(mx[1],u1); mn[1]=fminf(mn[1],u1);
            mx[2]=fmaxf(mx[2],u2); mn[2]=fminf(mn[2],u2);
            mx[3]=fmaxf(mx[3],u3); mn[3]=fminf(mn[3],u3);
        }
    #pragma unroll
    for (int o = 4; o; o >>= 1) {
        sum += __shfl_xor_sync(0xffffffffu, sum, o);
        sq  += __shfl_xor_sync(0xffffffffu, sq , o);
    }
    float mean = sum*(1.f/192.f);
    float var  = sq*(1.f/192.f) - mean*mean;
    float inv  = rsqrtf(var+1e-5f);
    #pragma unroll
    for (int p = 0; p < 2; p++)
        #pragma unroll
        for (int e = 0; e < 2; e++) {
            int c = quad*4 + 2*p + e, mi = 2*p + e;
            float scv = gg[c]*inv;
            float shv = gb[c] - mean*scv;
            g_h3p[((s*128+c)*4+ph)*2+pw] = scv>0.f ? mx[mi]*scv+shv : mn[mi]*scv+shv;
        }
}

// ===== fc: 16 rows/block, 64 blocks, 256 thr =====
__global__ void __launch_bounds__(256) k_fc(const float* __restrict__ w,
        const float* __restrict__ bias) {
    __shared__ float xs[16*65];
    __shared__ float wt[64*129];
    __shared__ float sred[8][8];
    int r0 = blockIdx.x*16, tid = threadIdx.x;
    int c = tid&127, rg = tid>>7, wrp = tid>>5, ln = tid&31;
    float acc[8];
    float b0 = bias[c];
    #pragma unroll
    for (int rr = 0; rr < 8; rr++) acc[rr] = b0;
    for (int k0 = 0; k0 < 1024; k0 += 64) {
        __syncthreads();
        for (int i = tid; i < 1024; i += 256) {
            int r = i>>6, kk = i&63;
            xs[r*65+kk] = g_h3p[(r0+r)*1024 + k0 + kk];
        }
        for (int i = tid; i < 8192; i += 256) {
            int j = i>>6, kk = i&63;
            wt[kk*129+j] = w[j*1024 + k0 + kk];
        }
        __syncthreads();
        for (int kk = 0; kk < 64; kk++) {
            float wv = wt[kk*129+c];
            #pragma unroll
            for (int rr = 0; rr < 8; rr++) acc[rr] += xs[(rg*8+rr)*65+kk]*wv;
        }
    }
    float v[8];
    #pragma unroll
    for (int rr = 0; rr < 8; rr++) v[rr] = selu_f(acc[rr]);
    #pragma unroll
    for (int rr = 0; rr < 8; rr++) {
        float ss = v[rr]*v[rr];
        #pragma unroll
        for (int o = 16; o; o >>= 1) ss += __shfl_xor_sync(0xffffffffu, ss, o);
        if (ln == 0) sred[wrp][rr] = ss;
    }
    __syncthreads();
    #pragma unroll
    for (int rr = 0; rr < 8; rr++) {
        float t = sred[rg*4+0][rr] + sred[rg*4+1][rr] + sred[rg*4+2][rr] + sred[rg*4+3][rr];
        float n = fmaxf(sqrtf(t), 1e-12f);
        g_e[(r0+rg*8+rr)*128 + c] = v[rr]/n;
    }
}

// ===== qkv: 16 rows/block, 64 blocks, PE on K =====
__global__ void __launch_bounds__(256) k_qkv(const float* __restrict__ wq,
        const float* __restrict__ bq, const float* __restrict__ wk,
        const float* __restrict__ bk, const float* __restrict__ wv,
        const float* __restrict__ bv) {
    __shared__ float es[16*132];
    __shared__ float wt[64*129];
    int r0 = blockIdx.x*16, tid = threadIdx.x;
    int c = tid&127, rg = tid>>7;
    for (int i = tid; i < 2048; i += 256) {
        int r = i>>7, d = i&127;
        es[r*132+d] = g_e[(r0+r)*128 + d];
    }
    const float* W[3] = {wq, wk, wv};
    const float* B[3] = {bq, bk, bv};
    float* O[3] = {g_q, g_k, g_v};
    for (int m = 0; m < 3; m++) {
        float acc[8];
        float b0 = B[m][c];
        #pragma unroll
        for (int rr = 0; rr < 8; rr++) acc[rr] = b0;
        for (int k0 = 0; k0 < 128; k0 += 64) {
            __syncthreads();
            for (int i = tid; i < 8192; i += 256) {
                int j = i>>6, kk = i&63;
                wt[kk*129+j] = W[m][j*128 + k0 + kk];
            }
            __syncthreads();
            for (int kk = 0; kk < 64; kk++) {
                float wvv = wt[kk*129+c];
                #pragma unroll
                for (int rr = 0; rr < 8; rr++) acc[rr] += es[(rg*8+rr)*132 + k0 + kk]*wvv;
            }
        }
        #pragma unroll
        for (int rr = 0; rr < 8; rr++) {
            int sr = r0 + rg*8 + rr;
            float u = selu_f(acc[rr]);
            if (m == 1) {
                float f = expf((float)(c & ~1) * (-9.210340371976184f/128.f));
                float ang = (float)sr * f;
                u += (c & 1) ? cosf(ang) : sinf(ang);
            }
            O[m][sr*128 + c] = u;
        }
    }
}

// ===== attn: 8 rows/block, 128 blocks =====
__global__ void __launch_bounds__(256) k_attn() {
    __shared__ __align__(16) float q8[8*132];
    __shared__ float p[8*1024];
    __shared__ float rinv[8];
    __shared__ float part[8*128];
    int r0 = blockIdx.x*8, tid = threadIdx.x;
    for (int i = tid; i < 1024; i += 256) {
        int r = i>>7, d = i&127;
        q8[r*132+d] = g_q[(r0+r)*128 + d];
    }
    __syncthreads();
    const float scale = 0.08838834764831845f;
    for (int t = tid; t < 1024; t += 256) {
        float a[8] = {0,0,0,0,0,0,0,0};
        const float4* kr = (const float4*)(g_k + t*128);
        #pragma unroll 8
        for (int d4 = 0; d4 < 32; d4++) {
            float4 kv = kr[d4];
            #pragma unroll
            for (int r = 0; r < 8; r++) {
                float4 qv = *(const float4*)&q8[r*132 + d4*4];
                a[r] += qv.x*kv.x + qv.y*kv.y + qv.z*kv.z + qv.w*kv.w;
            }
        }
        #pragma unroll
        for (int r = 0; r < 8; r++) p[r*1024+t] = a[r]*scale;
    }
    __syncthreads();
    int wrp = tid>>5, ln = tid&31;
    {
        int r = wrp;
        float mxv = -1e30f;
        for (int t = ln; t < 1024; t += 32) mxv = fmaxf(mxv, p[r*1024+t]);
        #pragma unroll
        for (int o = 16; o; o >>= 1) mxv = fmaxf(mxv, __shfl_xor_sync(0xffffffffu, mxv, o));
        float sm = 0.f;
        for (int t = ln; t < 1024; t += 32) {
            float e = expf(p[r*1024+t] - mxv);
            p[r*1024+t] = e;
            sm += e;
        }
        #pragma unroll
        for (int o = 16; o; o >>= 1) sm += __shfl_xor_sync(0xffffffffu, sm, o);
        if (ln == 0) rinv[r] = 1.f/sm;
    }
    __syncthreads();
    int c = tid&127, hf = tid>>7;
    float a[8] = {0,0,0,0,0,0,0,0};
    for (int t = hf*512; t < hf*512+512; t++) {
        float vv = g_v[t*128 + c];
        #pragma unroll
        for (int r = 0; r < 8; r++) a[r] += p[r*1024+t]*vv;
    }
    if (hf) {
        #pragma unroll
        for (int r = 0; r < 8; r++) part[r*128+c] = a[r];
    }
    __syncthreads();
    if (!hf) {
        #pragma unroll
        for (int r = 0; r < 8; r++)
            g_ao[(r0+r)*128+c] = (a[r] + part[r*128+c])*rinv[r];
    }
}

// ===== column l2norms: 128 blocks (one per column) =====
__global__ void __launch_bounds__(256) k_colfix() {
    __shared__ float red[8];
    __shared__ float sv;
    int d = blockIdx.x, tid = threadIdx.x, w = tid>>5, ln = tid&31;
    float ss = 0.f;
    for (int s = tid; s < 1024; s += 256) { float v = g_ao[s*128+d]; ss += v*v; }
    #pragma unroll
    for (int o = 16; o; o >>= 1) ss += __shfl_xor_sync(0xffffffffu, ss, o);
    if (ln == 0) red[w] = ss;
    __syncthreads();
    if (tid == 0) {
        float t = 0.f;
        for (int j = 0; j < 8; j++) t += red[j];
        sv = 1.f/fmaxf(sqrtf(t), 1e-12f);
    }
    __syncthreads();
    float inv1 = sv;
    float ss2 = 0.f;
    for (int s = tid; s < 1024; s += 256) {
        float v = g_ao[s*128+d]*inv1 + g_e[s*128+d];
        g_o2[s*128+d] = v;
        ss2 += v*v;
    }
    #pragma unroll
    for (int o = 16; o; o >>= 1) ss2 += __shfl_xor_sync(0xffffffffu, ss2, o);
    __syncthreads();
    if (ln == 0) red[w] = ss2;
    __syncthreads();
    if (tid == 0) {
        float t = 0.f;
        for (int j = 0; j < 8; j++) t += red[j];
        sv = 1.f/fmaxf(sqrtf(t), 1e-12f);
    }
    __syncthreads();
    float inv2 = sv;
    for (int s = tid; s < 1024; s += 256) g_ea[s*128+d] = g_o2[s*128+d]*inv2;
}

__global__ void k_rowsq() {
    int s = blockIdx.x*128 + threadIdx.x;
    const float4* r = (const float4*)(g_ea + s*128);
    float ss = 0.f;
    #pragma unroll
    for (int i = 0; i < 32; i++) {
        float4 v = r[i];
        ss += v.x*v.x + v.y*v.y + v.z*v.z + v.w*v.w;
    }
    g_sq[s] = ss;
}

__global__ void k_init() { g_dmax = 0u; }

__global__ void k_gram(float* __restrict__ dout) {
    __shared__ float ea_i[32][129];
    __shared__ float ea_j[32][129];
    __shared__ float sqi[32], sqj[32];
    __shared__ float rmax[8];
    int i0 = blockIdx.y*32, j0 = blockIdx.x*32;
    int tid = threadIdx.x;
    for (int idx = tid; idx < 4096; idx += 256) {
        int r = idx>>7, d = idx&127;
        ea_i[r][d] = g_ea[(i0+r)*128+d];
        ea_j[r][d] = g_ea[(j0+r)*128+d];
    }
    if (tid < 32) { sqi[tid] = g_sq[i0+tid]; sqj[tid] = g_sq[j0+tid]; }
    __syncthreads();
    int tx = tid&15, ty = tid>>4;
    int r0 = 2*ty, c0 = 2*tx;
    float d00 = 0.f, d01 = 0.f, d10 = 0.f, d11 = 0.f;
    #pragma unroll 4
    for (int d = 0; d < 128; d++) {
        float a0 = ea_i[r0][d], a1 = ea_i[r0+1][d];
        float b0 = ea_j[c0][d], b1 = ea_j[c0+1][d];
        d00 += a0*b0; d01 += a0*b1; d10 += a1*b0; d11 += a1*b1;
    }
    float lm = 0.f;
    float dots[4] = {d00, d01, d10, d11};
    #pragma unroll
    for (int u = 0; u < 4; u++) {
        int r = r0 + (u>>1), c = c0 + (u&1);
        float d2 = fmaxf(sqi[r] + sqj[c] - 2.f*dots[u], 0.f);
        float dd = sqrtf(d2 + 1e-12f);
        dout[(i0+r)*1024 + j0 + c] = dd;
        lm = fmaxf(lm, dd);
    }
    #pragma unroll
    for (int o = 16; o; o >>= 1) lm = fmaxf(lm, __shfl_xor_sync(0xffffffffu, lm, o));
    if ((tid&31) == 0) rmax[tid>>5] = lm;
    __syncthreads();
    if (tid == 0) {
        float m = 0.f;
        for (int i = 0; i < 8; i++) m = fmaxf(m, rmax[i]);
        atomicMax(&g_dmax, __float_as_uint(m));
    }
}

__global__ void k_final(float* __restrict__ dout) {
    float inv = 1.f/__uint_as_float(g_dmax);
    int i = blockIdx.x*256 + threadIdx.x;
    dout[i] = 1.f - dout[i]*inv;
}

extern "C" void kernel_launch(void* const* d_in, const int* in_sizes, int n_in,
                              void* d_out, int out_size) {
    const float* x   = (const float*)d_in[0];
    const float* c1w = (const float*)d_in[1];
    const float* c1b = (const float*)d_in[2];
    const float* g1g = (const float*)d_in[3];
    const float* g1b = (const float*)d_in[4];
    const float* c2w = (const float*)d_in[5];
    const float* c2b = (const float*)d_in[6];
    const float* g2g = (const float*)d_in[7];
    const float* g2b = (const float*)d_in[8];
    const float* c3w = (const float*)d_in[9];
    const float* c3b = (const float*)d_in[10];
    const float* g3g = (const float*)d_in[11];
    const float* g3b = (const float*)d_in[12];
    const float* fcw = (const float*)d_in[13];
    const float* fcb = (const float*)d_in[14];
    const float* wq  = (const float*)d_in[15];
    const float* bq  = (const float*)d_in[16];
    const float* wk  = (const float*)d_in[17];
    const float* bk  = (const float*)d_in[18];
    const float* wv  = (const float*)d_in[19];
    const float* bv  = (const float*)d_in[20];
    float* out = (float*)d_out;

    cudaFuncSetAttribute(k_conv3, cudaFuncAttributeMaxDynamicSharedMemorySize, 96*132*4);

    k_conv1<<<1024, 256>>>(x, c1w, c1b, g1g, g1b);
    k_conv2<<<dim3(1024,4), 192>>>(c2w, c2b, g2g, g2b);
    k_conv3<<<1024, 256, 96*132*4>>>(c3w, c3b, g3g, g3b);
    k_fc  <<<64, 256>>>(fcw, fcb);
    k_qkv <<<64, 256>>>(wq, bq, wk, bk, wv, bv);
    k_attn<<<128, 256>>>();
    k_colfix<<<128, 256>>>();
    k_rowsq<<<8, 128>>>();
    k_init<<<1, 1>>>();
    k_gram<<<dim3(32,32), 256>>>(out);
    k_final<<<4096, 256>>>(out);
}

// round 6
// speedup vs baseline: 3.5066x; 1.0019x over previous
#include <cuda_runtime.h>
#include <math.h>

#define NS 1024

__device__ float g_h1p[NS*32*36*16];
__device__ float g_h2p[NS*64*12*4];
__device__ float g_h3p[NS*128*4*2];
__device__ float g_e [NS*128];
__device__ float g_q [NS*128];
__device__ float g_k [NS*128];
__device__ float g_v [NS*128];
__device__ float g_ao[NS*128];
__device__ float g_o2[NS*128];
__device__ float g_ea[NS*128];
__device__ float g_sq[NS];
__device__ float g_css[128];
__device__ float g_css2[128];
__device__ unsigned int g_dmax;

__device__ __forceinline__ float selu_f(float x) {
    const float a = 1.6732632423543772f, sc = 1.0507009873554805f;
    return x > 0.f ? sc * x : sc * a * (expf(x) - 1.f);
}

__device__ __forceinline__ float2 ffma2(float2 a, float2 b, float2 c) {
    unsigned long long ua = *(unsigned long long*)&a;
    unsigned long long ub = *(unsigned long long*)&b;
    unsigned long long uc = *(unsigned long long*)&c;
    unsigned long long ud;
    asm("fma.rn.f32x2 %0, %1, %2, %3;" : "=l"(ud) : "l"(ua), "l"(ub), "l"(uc));
    return *(float2*)&ud;
}

__global__ void k_zero() {
    int t = threadIdx.x;
    if (t < 128) { g_css[t] = 0.f; g_css2[t] = 0.f; }
    if (t == 255) g_dmax = 0u;
}

// ===== conv1: 1 block/frame, 32 ch =====
__global__ void __launch_bounds__(256) k_conv1(const float* __restrict__ x,
        const float* __restrict__ w, const float* __restrict__ bias,
        const float* __restrict__ gg, const float* __restrict__ gb) {
    __shared__ float pad[77*67];
    int s = blockIdx.x, tid = threadIdx.x, lane = tid & 31;
    const float* xs = x + s*4608;
    for (int i = tid; i < 77*67; i += 256) {
        int r = i/67, cc = i - r*67;
        int ih = r-2, iw = cc-1;
        pad[i] = (ih>=0 && ih<72 && iw>=0 && iw<64) ? xs[ih*64+iw] : 0.f;
    }
    __syncthreads();
    for (int cc4 = 0; cc4 < 4; cc4++) {
        int ch = cc4*8 + (tid>>5);
        float2 w2[24];
        #pragma unroll
        for (int k2 = 0; k2 < 24; k2++) { float wv = w[ch*24+k2]; w2[k2] = make_float2(wv, wv); }
        float bi = bias[ch];
        float pm[18], pn[18], sum = 0.f, sq = 0.f;
        for (int wi = 0; wi < 18; wi++) {
            int wdw = wi*32 + lane;
            int ph = wdw>>4, pw = wdw&15;
            float2 acc[2][2];
            #pragma unroll
            for (int r = 0; r < 2; r++)
                #pragma unroll
                for (int cp = 0; cp < 2; cp++) acc[r][cp] = make_float2(bi, bi);
            #pragma unroll
            for (int ir = 0; ir < 7; ir++) {
                const float* pr = &pad[(2*ph+ir)*67 + 4*pw];
                float v[7];
                #pragma unroll
                for (int j = 0; j < 7; j++) v[j] = pr[j];
                #pragma unroll
                for (int r = 0; r < 2; r++) {
                    int kh = ir - r;
                    if (kh >= 0 && kh < 6) {
                        #pragma unroll
                        for (int kw = 0; kw < 4; kw++) {
                            float2 wv = w2[kh*4+kw];
                            #pragma unroll
                            for (int cp = 0; cp < 2; cp++)
                                acc[r][cp] = ffma2(make_float2(v[2*cp+kw], v[2*cp+kw+1]), wv, acc[r][cp]);
                        }
                    }
                }
            }
            float mx = -1e30f, mn = 1e30f;
            #pragma unroll
            for (int r = 0; r < 2; r++)
                #pragma unroll
                for (int cp = 0; cp < 2; cp++) {
                    float u0 = selu_f(acc[r][cp].x), u1 = selu_f(acc[r][cp].y);
                    sum += u0+u1; sq += u0*u0+u1*u1;
                    mx = fmaxf(mx, fmaxf(u0,u1)); mn = fminf(mn, fminf(u0,u1));
                }
            pm[wi] = mx; pn[wi] = mn;
        }
        #pragma unroll
        for (int o = 16; o; o >>= 1) {
            sum += __shfl_xor_sync(0xffffffffu, sum, o);
            sq  += __shfl_xor_sync(0xffffffffu, sq , o);
        }
        float mean = sum*(1.f/4608.f);
        float var  = sq*(1.f/4608.f) - mean*mean;
        float sc = gg[ch]*rsqrtf(var+1e-5f);
        float sh = gb[ch] - mean*sc;
        for (int wi = 0; wi < 18; wi++) {
            int wdw = wi*32 + lane;
            int ph = wdw>>4, pw = wdw&15;
            g_h1p[((s*32+ch)*36+ph)*16+pw] = sc>0.f ? pm[wi]*sc+sh : pn[wi]*sc+sh;
        }
    }
}

// ===== conv2: 2 frames/block, 16 oc, grid (512,4), 384 thr, dyn smem =====
// dyn layout: pad[12464] | ws[3840]; red aliased onto pad after compute
#define C2_SMEM ((12464+3840)*4)
__global__ void __launch_bounds__(384) k_conv2(const float* __restrict__ w,
        const float* __restrict__ bias, const float* __restrict__ gg,
        const float* __restrict__ gb) {
    extern __shared__ float dsm[];
    float* pad = dsm;
    float* ws  = dsm + 12464;
    float4* red = (float4*)dsm;
    __shared__ float gnsc[2][16], gnsh[2][16];
    int s0 = blockIdx.x*2, ocb = 16*blockIdx.y, tid = threadIdx.x;
    int fr = tid >= 192 ? 1 : 0;
    int t2 = tid - fr*192;
    int quad = t2/48, wdw = t2 - quad*48;
    int ph = wdw>>2, pw = wdw&3;
    const float* padf = pad + fr*6232;
    float2 acc[3][4][2];
    #pragma unroll
    for (int p = 0; p < 2; p++) {
        float2 b2 = make_float2(bias[ocb+quad*4+2*p], bias[ocb+quad*4+2*p+1]);
        #pragma unroll
        for (int r = 0; r < 3; r++)
            #pragma unroll
            for (int c = 0; c < 4; c++) acc[r][c][p] = b2;
    }
    for (int ck = 0; ck < 4; ck++) {
        int ic0 = 8*ck;
        __syncthreads();
        for (int i = tid; i < 3072; i += 384) {
            int oc = i/192, r = i - oc*192;
            ws[r*20+oc] = w[(ocb+oc)*768 + ic0*24 + r];
        }
        for (int i = tid; i < 12464; i += 384) {
            int f = i/6232, rem = i - f*6232;
            int icl = rem/779, rem2 = rem - icl*779;
            int rr = rem2/19, cc = rem2 - rr*19;
            int ih = rr-2, iw = cc-1;
            pad[i] = (ih>=0 && ih<36 && iw>=0 && iw<16)
                   ? g_h1p[(((s0+f)*32+ic0+icl)*36+ih)*16+iw] : 0.f;
        }
        __syncthreads();
        #pragma unroll 1
        for (int icl = 0; icl < 8; icl++) {
            const float* pb = padf + icl*779;
            #pragma unroll
            for (int kh = 0; kh < 6; kh++) {
                float4 wv[4];
                #pragma unroll
                for (int kw = 0; kw < 4; kw++)
                    wv[kw] = *(const float4*)&ws[(icl*24+kh*4+kw)*20 + 4*quad];
                #pragma unroll
                for (int r = 0; r < 3; r++) {
                    const float* pr = pb + (3*ph+r+kh)*19 + 4*pw;
                    float v[7];
                    #pragma unroll
                    for (int j = 0; j < 7; j++) v[j] = pr[j];
                    #pragma unroll
                    for (int c = 0; c < 4; c++)
                        #pragma unroll
                        for (int kw = 0; kw < 4; kw++) {
                            float2 t = make_float2(v[c+kw], v[c+kw]);
                            acc[r][c][0] = ffma2(t, make_float2(wv[kw].x, wv[kw].y), acc[r][c][0]);
                            acc[r][c][1] = ffma2(t, make_float2(wv[kw].z, wv[kw].w), acc[r][c][1]);
                        }
                }
            }
        }
    }
    float s01 = 0.f, q01 = 0.f, s23 = 0.f, q23 = 0.f;
    float mx[4] = {-1e30f,-1e30f,-1e30f,-1e30f};
    float mn[4] = { 1e30f, 1e30f, 1e30f, 1e30f};
    #pragma unroll
    for (int r = 0; r < 3; r++)
        #pragma unroll
        for (int c = 0; c < 4; c++) {
            float u0 = selu_f(acc[r][c][0].x), u1 = selu_f(acc[r][c][0].y);
            float u2 = selu_f(acc[r][c][1].x), u3 = selu_f(acc[r][c][1].y);
            s01 += u0+u1; q01 += u0*u0+u1*u1;
            s23 += u2+u3; q23 += u2*u2+u3*u3;
            mx[0]=fmaxf(mx[0],u0); mn[0]=fminf(mn[0],u0);
            mx[1]=fmaxf(mx[1],u1); mn[1]=fminf(mn[1],u1);
            mx[2]=fmaxf(mx[2],u2); mn[2]=fminf(mn[2],u2);
            mx[3]=fmaxf(mx[3],u3); mn[3]=fminf(mn[3],u3);
        }
    __syncthreads();   // pad dead; safe to alias red
    red[tid] = make_float4(s01, q01, s23, q23);
    __syncthreads();
    if (tid < 16) {
        int fr2 = tid>>3, t3 = tid&7, qd = t3>>1;
        float sm = 0.f, sv = 0.f;
        for (int j = 0; j < 48; j++) {
            float4 f = red[fr2*192 + qd*48 + j];
            if (t3 & 1) { sm += f.z; sv += f.w; } else { sm += f.x; sv += f.y; }
        }
        float mean = sm*(1.f/1152.f);
        float var  = sv*(1.f/1152.f) - mean*mean;
        float inv  = rsqrtf(var+1e-5f);
        for (int j = 0; j < 2; j++) {
            int lc = 2*t3 + j;
            float scv = gg[ocb+lc]*inv;
            gnsc[fr2][lc] = scv; gnsh[fr2][lc] = gb[ocb+lc] - mean*scv;
        }
    }
    __syncthreads();
    #pragma unroll
    for (int p = 0; p < 2; p++)
        #pragma unroll
        for (int e = 0; e < 2; e++) {
            int lc = quad*4 + 2*p + e, mi = 2*p + e;
            float scv = gnsc[fr][lc], shv = gnsh[fr][lc];
            g_h2p[(((s0+fr)*64+ocb+lc)*12+ph)*4+pw] = scv>0.f ? mx[mi]*scv+shv : mn[mi]*scv+shv;
        }
}

// ===== conv3: 2 frames/block, 128 oc, grid 512, 512 thr =====
__global__ void __launch_bounds__(512) k_conv3(const float* __restrict__ w,
        const float* __restrict__ bias, const float* __restrict__ gg,
        const float* __restrict__ gb) {
    extern __shared__ float ws[];   // 96*132
    __shared__ float pad[952];
    int tid = threadIdx.x;
    int fr = tid>>8, t2 = tid&255;
    int s = blockIdx.x*2 + fr;
    int quad = t2>>3, wdw = t2&7;
    int ph = wdw>>1, pw = wdw&1;
    float2 acc[3][2][2];
    #pragma unroll
    for (int p = 0; p < 2; p++) {
        float2 b2 = make_float2(bias[quad*4+2*p], bias[quad*4+2*p+1]);
        #pragma unroll
        for (int r = 0; r < 3; r++)
            #pragma unroll
            for (int c = 0; c < 2; c++) acc[r][c][p] = b2;
    }
    for (int ck = 0; ck < 16; ck++) {
        int ic0 = 4*ck;
        __syncthreads();
        for (int i = tid; i < 12288; i += 512) {
            int oc = i/96, r = i - oc*96;
            ws[r*132+oc] = w[oc*1536 + ic0*24 + r];
        }
        for (int i = tid; i < 952; i += 512) {
            int f = i/476, rem = i - f*476;
            int icl = rem/119, rem2 = rem - icl*119;
            int rr = rem2/7, cc = rem2 - rr*7;
            int ih = rr-2, iw = cc-1;
            pad[i] = (ih>=0 && ih<12 && iw>=0 && iw<4)
                   ? g_h2p[(((blockIdx.x*2+f)*64+ic0+icl)*12+ih)*4+iw] : 0.f;
        }
        __syncthreads();
        #pragma unroll 1
        for (int icl = 0; icl < 4; icl++) {
            const float* pb = pad + fr*476 + icl*119;
            #pragma unroll
            for (int kh = 0; kh < 6; kh++) {
                float4 wv[4];
                #pragma unroll
                for (int kw = 0; kw < 4; kw++)
                    wv[kw] = *(const float4*)&ws[(icl*24+kh*4+kw)*132 + 4*quad];
                #pragma unroll
                for (int r = 0; r < 3; r++) {
                    const float* pr = pb + (3*ph+r+kh)*7 + 2*pw;
                    float v[5];
                    #pragma unroll
                    for (int j = 0; j < 5; j++) v[j] = pr[j];
                    #pragma unroll
                    for (int c = 0; c < 2; c++)
                        #pragma unroll
                        for (int kw = 0; kw < 4; kw++) {
                            float2 t = make_float2(v[c+kw], v[c+kw]);
                            acc[r][c][0] = ffma2(t, make_float2(wv[kw].x, wv[kw].y), acc[r][c][0]);
                            acc[r][c][1] = ffma2(t, make_float2(wv[kw].z, wv[kw].w), acc[r][c][1]);
                        }
                }
            }
        }
    }
    float sum = 0.f, sq = 0.f;
    float mx[4] = {-1e30f,-1e30f,-1e30f,-1e30f};
    float mn[4] = { 1e30f, 1e30f, 1e30f, 1e30f};
    #pragma unroll
    for (int r = 0; r < 3; r++)
        #pragma unroll
        for (int c = 0; c < 2; c++) {
            float u0 = selu_f(acc[r][c][0].x), u1 = selu_f(acc[r][c][0].y);
            float u2 = selu_f(acc[r][c][1].x), u3 = selu_f(acc[r][c][1].y);
            sum += u0+u1+u2+u3; sq += u0*u0+u1*u1+u2*u2+u3*u3;
            mx[0]=fmaxf(mx[0],u0); mn[0]=fminf(mn[0],u0);
            mx[1]=fmaxf(mx[1],u1); mn[1]=fminf(mn[1],u1);
            mx[2]=fmaxf(mx[2],u2); mn[2]=fminf(mn[2],u2);
            mx[3]=fmaxf(mx[3],u3); mn[3]=fminf(mn[3],u3);
        }
    #pragma unroll
    for (int o = 4; o; o >>= 1) {
        sum += __shfl_xor_sync(0xffffffffu, sum, o);
        sq  += __shfl_xor_sync(0xffffffffu, sq , o);
    }
    float mean = sum*(1.f/192.f);
    float var  = sq*(1.f/192.f) - mean*mean;
    float inv  = rsqrtf(var+1e-5f);
    #pragma unroll
    for (int p = 0; p < 2; p++)
        #pragma unroll
        for (int e = 0; e < 2; e++) {
            int c = quad*4 + 2*p + e, mi = 2*p + e;
            float scv = gg[c]*inv;
            float shv = gb[c] - mean*scv;
            g_h3p[((s*128+c)*4+ph)*2+pw] = scv>0.f ? mx[mi]*scv+shv : mn[mi]*scv+shv;
        }
}

// ===== fc: 8 rows/block, 128 blocks =====
__global__ void __launch_bounds__(256) k_fc(const float* __restrict__ w,
        const float* __restrict__ bias) {
    __shared__ float xs[8*65];
    __shared__ float wt[64*129];
    __shared__ float sred[8][4];
    int r0 = blockIdx.x*8, tid = threadIdx.x;
    int c = tid&127, rg = tid>>7, wrp = tid>>5, ln = tid&31;
    float acc[4];
    float b0 = bias[c];
    #pragma unroll
    for (int rr = 0; rr < 4; rr++) acc[rr] = b0;
    for (int k0 = 0; k0 < 1024; k0 += 64) {
        __syncthreads();
        for (int i = tid; i < 512; i += 256) {
            int r = i>>6, kk = i&63;
            xs[r*65+kk] = g_h3p[(r0+r)*1024 + k0 + kk];
        }
        for (int i = tid; i < 8192; i += 256) {
            int j = i>>6, kk = i&63;
            wt[kk*129+j] = w[j*1024 + k0 + kk];
        }
        __syncthreads();
        for (int kk = 0; kk < 64; kk++) {
            float wv = wt[kk*129+c];
            #pragma unroll
            for (int rr = 0; rr < 4; rr++) acc[rr] += xs[(rg*4+rr)*65+kk]*wv;
        }
    }
    float v[4];
    #pragma unroll
    for (int rr = 0; rr < 4; rr++) v[rr] = selu_f(acc[rr]);
    #pragma unroll
    for (int rr = 0; rr < 4; rr++) {
        float ss = v[rr]*v[rr];
        #pragma unroll
        for (int o = 16; o; o >>= 1) ss += __shfl_xor_sync(0xffffffffu, ss, o);
        if (ln == 0) sred[wrp][rr] = ss;
    }
    __syncthreads();
    #pragma unroll
    for (int rr = 0; rr < 4; rr++) {
        float t = sred[rg*4+0][rr] + sred[rg*4+1][rr] + sred[rg*4+2][rr] + sred[rg*4+3][rr];
        float n = fmaxf(sqrtf(t), 1e-12f);
        g_e[(r0+rg*4+rr)*128 + c] = v[rr]/n;
    }
}

// ===== qkv: 8 rows/block, 128 blocks =====
__global__ void __launch_bounds__(256) k_qkv(const float* __restrict__ wq,
        const float* __restrict__ bq, const float* __restrict__ wk,
        const float* __restrict__ bk, const float* __restrict__ wv,
        const float* __restrict__ bv) {
    __shared__ float es[8*132];
    __shared__ float wt[64*129];
    int r0 = blockIdx.x*8, tid = threadIdx.x;
    int c = tid&127, rg = tid>>7;
    for (int i = tid; i < 1024; i += 256) {
        int r = i>>7, d = i&127;
        es[r*132+d] = g_e[(r0+r)*128 + d];
    }
    const float* W[3] = {wq, wk, wv};
    const float* B[3] = {bq, bk, bv};
    float* O[3] = {g_q, g_k, g_v};
    for (int m = 0; m < 3; m++) {
        float acc[4];
        float b0 = B[m][c];
        #pragma unroll
        for (int rr = 0; rr < 4; rr++) acc[rr] = b0;
        for (int k0 = 0; k0 < 128; k0 += 64) {
            __syncthreads();
            for (int i = tid; i < 8192; i += 256) {
                int j = i>>6, kk = i&63;
                wt[kk*129+j] = W[m][j*128 + k0 + kk];
            }
            __syncthreads();
            for (int kk = 0; kk < 64; kk++) {
                float wvv = wt[kk*129+c];
                #pragma unroll
                for (int rr = 0; rr < 4; rr++) acc[rr] += es[(rg*4+rr)*132 + k0 + kk]*wvv;
            }
        }
        #pragma unroll
        for (int rr = 0; rr < 4; rr++) {
            int sr = r0 + rg*4 + rr;
            float u = selu_f(acc[rr]);
            if (m == 1) {
                float f = expf((float)(c & ~1) * (-9.210340371976184f/128.f));
                float ang = (float)sr * f;
                u += (c & 1) ? cosf(ang) : sinf(ang);
            }
            O[m][sr*128 + c] = u;
        }
    }
}

// ===== attn: 8 rows/block, 128 blocks =====
__global__ void __launch_bounds__(256) k_attn() {
    __shared__ __align__(16) float q8[8*132];
    __shared__ float p[8*1024];
    __shared__ float rinv[8];
    __shared__ float part[8*128];
    int r0 = blockIdx.x*8, tid = threadIdx.x;
    for (int i = tid; i < 1024; i += 256) {
        int r = i>>7, d = i&127;
        q8[r*132+d] = g_q[(r0+r)*128 + d];
    }
    __syncthreads();
    const float scale = 0.08838834764831845f;
    for (int t = tid; t < 1024; t += 256) {
        float a[8] = {0,0,0,0,0,0,0,0};
        const float4* kr = (const float4*)(g_k + t*128);
        #pragma unroll 8
        for (int d4 = 0; d4 < 32; d4++) {
            float4 kv = kr[d4];
            #pragma unroll
            for (int r = 0; r < 8; r++) {
                float4 qv = *(const float4*)&q8[r*132 + d4*4];
                a[r] += qv.x*kv.x + qv.y*kv.y + qv.z*kv.z + qv.w*kv.w;
            }
        }
        #pragma unroll
        for (int r = 0; r < 8; r++) p[r*1024+t] = a[r]*scale;
    }
    __syncthreads();
    int wrp = tid>>5, ln = tid&31;
    {
        int r = wrp;
        float mxv = -1e30f;
        for (int t = ln; t < 1024; t += 32) mxv = fmaxf(mxv, p[r*1024+t]);
        #pragma unroll
        for (int o = 16; o; o >>= 1) mxv = fmaxf(mxv, __shfl_xor_sync(0xffffffffu, mxv, o));
        float sm = 0.f;
        for (int t = ln; t < 1024; t += 32) {
            float e = expf(p[r*1024+t] - mxv);
            p[r*1024+t] = e;
            sm += e;
        }
        #pragma unroll
        for (int o = 16; o; o >>= 1) sm += __shfl_xor_sync(0xffffffffu, sm, o);
        if (ln == 0) rinv[r] = 1.f/sm;
    }
    __syncthreads();
    int c = tid&127, hf = tid>>7;
    float a[8] = {0,0,0,0,0,0,0,0};
    for (int t = hf*512; t < hf*512+512; t++) {
        float vv = g_v[t*128 + c];
        #pragma unroll
        for (int r = 0; r < 8; r++) a[r] += p[r*1024+t]*vv;
    }
    if (hf) {
        #pragma unroll
        for (int r = 0; r < 8; r++) part[r*128+c] = a[r];
    }
    __syncthreads();
    if (!hf) {
        #pragma unroll
        for (int r = 0; r < 8; r++)
            g_ao[(r0+r)*128+c] = (a[r] + part[r*128+c])*rinv[r];
    }
}

__global__ void __launch_bounds__(256) k_cs1() {
    __shared__ float red[128];
    int s0 = blockIdx.x*16, tid = threadIdx.x;
    int c = tid&127, sy = tid>>7;
    float ss = 0.f;
    for (int s = sy; s < 16; s += 2) { float v = g_ao[(s0+s)*128+c]; ss += v*v; }
    if (sy) red[c] = ss;
    __syncthreads();
    if (!sy) atomicAdd(&g_css[c], ss + red[c]);
}

__global__ void __launch_bounds__(256) k_cs2() {
    __shared__ float red[128];
    int s0 = blockIdx.x*16, tid = threadIdx.x;
    int c = tid&127, sy = tid>>7;
    float inv1 = 1.f/fmaxf(sqrtf(g_css[c]), 1e-12f);
    float ss = 0.f;
    for (int s = sy; s < 16; s += 2) {
        float v = g_ao[(s0+s)*128+c]*inv1 + g_e[(s0+s)*128+c];
        g_o2[(s0+s)*128+c] = v;
        ss += v*v;
    }
    if (sy) red[c] = ss;
    __syncthreads();
    if (!sy) atomicAdd(&g_css2[c], ss + red[c]);
}

__global__ void __launch_bounds__(256) k_cs3() {
    int i = blockIdx.x*256 + threadIdx.x;
    int c = i&127;
    float inv2 = 1.f/fmaxf(sqrtf(g_css2[c]), 1e-12f);
    g_ea[i] = g_o2[i]*inv2;
}

__global__ void k_rowsq() {
    int s = blockIdx.x*128 + threadIdx.x;
    const float4* r = (const float4*)(g_ea + s*128);
    float ss = 0.f;
    #pragma unroll
    for (int i = 0; i < 32; i++) {
        float4 v = r[i];
        ss += v.x*v.x + v.y*v.y + v.z*v.z + v.w*v.w;
    }
    g_sq[s] = ss;
}

__global__ void k_gram(float* __restrict__ dout) {
    __shared__ float ea_i[32][129];
    __shared__ float ea_j[32][129];
    __shared__ float sqi[32], sqj[32];
    __shared__ float rmax[8];
    int i0 = blockIdx.y*32, j0 = blockIdx.x*32;
    int tid = threadIdx.x;
    for (int idx = tid; idx < 4096; idx += 256) {
        int r = idx>>7, d = idx&127;
        ea_i[r][d] = g_ea[(i0+r)*128+d];
        ea_j[r][d] = g_ea[(j0+r)*128+d];
    }
    if (tid < 32) { sqi[tid] = g_sq[i0+tid]; sqj[tid] = g_sq[j0+tid]; }
    __syncthreads();
    int tx = tid&15, ty = tid>>4;
    int r0 = 2*ty, c0 = 2*tx;
    float d00 = 0.f, d01 = 0.f, d10 = 0.f, d11 = 0.f;
    #pragma unroll 4
    for (int d = 0; d < 128; d++) {
        float a0 = ea_i[r0][d], a1 = ea_i[r0+1][d];
        float b0 = ea_j[c0][d], b1 = ea_j[c0+1][d];
        d00 += a0*b0; d01 += a0*b1; d10 += a1*b0; d11 += a1*b1;
    }
    float lm = 0.f;
    float dots[4] = {d00, d01, d10, d11};
    #pragma unroll
    for (int u = 0; u < 4; u++) {
        int r = r0 + (u>>1), c = c0 + (u&1);
        float d2 = fmaxf(sqi[r] + sqj[c] - 2.f*dots[u], 0.f);
        float dd = sqrtf(d2 + 1e-12f);
        dout[(i0+r)*1024 + j0 + c] = dd;
        lm = fmaxf(lm, dd);
    }
    #pragma unroll
    for (int o = 16; o; o >>= 1) lm = fmaxf(lm, __shfl_xor_sync(0xffffffffu, lm, o));
    if ((tid&31) == 0) rmax[tid>>5] = lm;
    __syncthreads();
    if (tid == 0) {
        float m = 0.f;
        for (int i = 0; i < 8; i++) m = fmaxf(m, rmax[i]);
        atomicMax(&g_dmax, __float_as_uint(m));
    }
}

__global__ void k_final(float* __restrict__ dout) {
    float inv = 1.f/__uint_as_float(g_dmax);
    int i = blockIdx.x*256 + threadIdx.x;
    dout[i] = 1.f - dout[i]*inv;
}

extern "C" void kernel_launch(void* const* d_in, const int* in_sizes, int n_in,
                              void* d_out, int out_size) {
    const float* x   = (const float*)d_in[0];
    const float* c1w = (const float*)d_in[1];
    const float* c1b = (const float*)d_in[2];
    const float* g1g = (const float*)d_in[3];
    const float* g1b = (const float*)d_in[4];
    const float* c2w = (const float*)d_in[5];
    const float* c2b = (const float*)d_in[6];
    const float* g2g = (const float*)d_in[7];
    const float* g2b = (const float*)d_in[8];
    const float* c3w = (const float*)d_in[9];
    const float* c3b = (const float*)d_in[10];
    const float* g3g = (const float*)d_in[11];
    const float* g3b = (const float*)d_in[12];
    const float* fcw = (const float*)d_in[13];
    const float* fcb = (const float*)d_in[14];
    const float* wq  = (const float*)d_in[15];
    const float* bq  = (const float*)d_in[16];
    const float* wk  = (const float*)d_in[17];
    const float* bk  = (const float*)d_in[18];
    const float* wv  = (const float*)d_in[19];
    const float* bv  = (const float*)d_in[20];
    float* out = (float*)d_out;

    cudaFuncSetAttribute(k_conv2, cudaFuncAttributeMaxDynamicSharedMemorySize, C2_SMEM);
    cudaFuncSetAttribute(k_conv3, cudaFuncAttributeMaxDynamicSharedMemorySize, 96*132*4);

    k_zero<<<1, 256>>>();
    k_conv1<<<1024, 256>>>(x, c1w, c1b, g1g, g1b);
    k_conv2<<<dim3(512,4), 384, C2_SMEM>>>(c2w, c2b, g2g, g2b);
    k_conv3<<<512, 512, 96*132*4>>>(c3w, c3b, g3g, g3b);
    k_fc  <<<128, 256>>>(fcw, fcb);
    k_qkv <<<128, 256>>>(wq, bq, wk, bk, wv, bv);
    k_attn<<<128, 256>>>();
    k_cs1 <<<64, 256>>>();
    k_cs2 <<<64, 256>>>();
    k_cs3 <<<512, 256>>>();
    k_rowsq<<<8, 128>>>();
    k_gram<<<dim3(32,32), 256>>>(out);
    k_final<<<4096, 256>>>(out);
}

// round 7
// speedup vs baseline: 4.6200x; 1.3175x over previous
#include <cuda_runtime.h>
#include <math.h>

#define NS 1024

__device__ float g_h1p[NS*32*36*16];
__device__ float g_c2 [NS*64*576];
__device__ float g_h2p[NS*64*12*4];
__device__ float g_h3p[NS*128*4*2];
__device__ float g_e [NS*128];
__device__ float g_q [NS*128];
__device__ float g_k [NS*128];
__device__ float g_v [NS*128];
__device__ float g_ao[NS*128];
__device__ float g_o2[NS*128];
__device__ float g_ea[NS*128];
__device__ float g_sq[NS];
__device__ float g_css[128];
__device__ float g_css2[128];
__device__ unsigned int g_dmax;

__device__ __forceinline__ float selu_f(float x) {
    const float a = 1.6732632423543772f, sc = 1.0507009873554805f;
    return x > 0.f ? sc * x : sc * a * (expf(x) - 1.f);
}

__device__ __forceinline__ float2 ffma2(float2 a, float2 b, float2 c) {
    unsigned long long ua = *(unsigned long long*)&a;
    unsigned long long ub = *(unsigned long long*)&b;
    unsigned long long uc = *(unsigned long long*)&c;
    unsigned long long ud;
    asm("fma.rn.f32x2 %0, %1, %2, %3;" : "=l"(ud) : "l"(ua), "l"(ub), "l"(uc));
    return *(float2*)&ud;
}

__device__ __forceinline__ unsigned tf32c(float x) {
    unsigned u; asm("cvt.rna.tf32.f32 %0, %1;" : "=r"(u) : "f"(x)); return u;
}
__device__ __forceinline__ void mma_tf32(float* d, const unsigned* a, const unsigned* b) {
    asm volatile("mma.sync.aligned.m16n8k8.row.col.f32.tf32.tf32.f32 "
        "{%0,%1,%2,%3}, {%4,%5,%6,%7}, {%8,%9}, {%0,%1,%2,%3};"
        : "+f"(d[0]), "+f"(d[1]), "+f"(d[2]), "+f"(d[3])
        : "r"(a[0]), "r"(a[1]), "r"(a[2]), "r"(a[3]), "r"(b[0]), "r"(b[1]));
}

__global__ void k_zero() {
    int t = threadIdx.x;
    if (t < 128) { g_css[t] = 0.f; g_css2[t] = 0.f; }
    if (t == 255) g_dmax = 0u;
}

// ===== conv1: 1 block/frame, 32 ch (FFMA2 path) =====
__global__ void __launch_bounds__(256) k_conv1(const float* __restrict__ x,
        const float* __restrict__ w, const float* __restrict__ bias,
        const float* __restrict__ gg, const float* __restrict__ gb) {
    __shared__ float pad[77*67];
    int s = blockIdx.x, tid = threadIdx.x, lane = tid & 31;
    const float* xs = x + s*4608;
    for (int i = tid; i < 77*67; i += 256) {
        int r = i/67, cc = i - r*67;
        int ih = r-2, iw = cc-1;
        pad[i] = (ih>=0 && ih<72 && iw>=0 && iw<64) ? xs[ih*64+iw] : 0.f;
    }
    __syncthreads();
    for (int cc4 = 0; cc4 < 4; cc4++) {
        int ch = cc4*8 + (tid>>5);
        float2 w2[24];
        #pragma unroll
        for (int k2 = 0; k2 < 24; k2++) { float wv = w[ch*24+k2]; w2[k2] = make_float2(wv, wv); }
        float bi = bias[ch];
        float pm[18], pn[18], sum = 0.f, sq = 0.f;
        for (int wi = 0; wi < 18; wi++) {
            int wdw = wi*32 + lane;
            int ph = wdw>>4, pw = wdw&15;
            float2 acc[2][2];
            #pragma unroll
            for (int r = 0; r < 2; r++)
                #pragma unroll
                for (int cp = 0; cp < 2; cp++) acc[r][cp] = make_float2(bi, bi);
            #pragma unroll
            for (int ir = 0; ir < 7; ir++) {
                const float* pr = &pad[(2*ph+ir)*67 + 4*pw];
                float v[7];
                #pragma unroll
                for (int j = 0; j < 7; j++) v[j] = pr[j];
                #pragma unroll
                for (int r = 0; r < 2; r++) {
                    int kh = ir - r;
                    if (kh >= 0 && kh < 6) {
                        #pragma unroll
                        for (int kw = 0; kw < 4; kw++) {
                            float2 wv = w2[kh*4+kw];
                            #pragma unroll
                            for (int cp = 0; cp < 2; cp++)
                                acc[r][cp] = ffma2(make_float2(v[2*cp+kw], v[2*cp+kw+1]), wv, acc[r][cp]);
                        }
                    }
                }
            }
            float mx = -1e30f, mn = 1e30f;
            #pragma unroll
            for (int r = 0; r < 2; r++)
                #pragma unroll
                for (int cp = 0; cp < 2; cp++) {
                    float u0 = selu_f(acc[r][cp].x), u1 = selu_f(acc[r][cp].y);
                    sum += u0+u1; sq += u0*u0+u1*u1;
                    mx = fmaxf(mx, fmaxf(u0,u1)); mn = fminf(mn, fminf(u0,u1));
                }
            pm[wi] = mx; pn[wi] = mn;
        }
        #pragma unroll
        for (int o = 16; o; o >>= 1) {
            sum += __shfl_xor_sync(0xffffffffu, sum, o);
            sq  += __shfl_xor_sync(0xffffffffu, sq , o);
        }
        float mean = sum*(1.f/4608.f);
        float var  = sq*(1.f/4608.f) - mean*mean;
        float sc = gg[ch]*rsqrtf(var+1e-5f);
        float sh = gb[ch] - mean*sc;
        for (int wi = 0; wi < 18; wi++) {
            int wdw = wi*32 + lane;
            int ph = wdw>>4, pw = wdw&15;
            g_h1p[((s*32+ch)*36+ph)*16+pw] = sc>0.f ? pm[wi]*sc+sh : pn[wi]*sc+sh;
        }
    }
}

// ===== conv2: TF32 implicit-GEMM mma. grid (1024, 2 oc-halves, 2 pos-halves), 256 thr =====
#define C2WS 33
__global__ void __launch_bounds__(256) k_conv2mma(const float* __restrict__ w2,
        const float* __restrict__ bias) {
    __shared__ float ws[192*C2WS];   // [k 0..191][oc 0..31]
    __shared__ float padc[8*437];    // 8 ic x 23 rows x 19 cols
    int s = blockIdx.x, ocb = 32*blockIdx.y, prow0 = 18*blockIdx.z;
    int tid = threadIdx.x, wrp = tid>>5, t = tid&31;
    int m = wrp & 1, ng = wrp >> 1;
    float cfr[9][4];
    #pragma unroll
    for (int j = 0; j < 9; j++) { cfr[j][0]=cfr[j][1]=cfr[j][2]=cfr[j][3]=0.f; }
    int off[9];
    #pragma unroll
    for (int j = 0; j < 9; j++) {
        int n = ng*72 + j*8 + (t>>2);
        off[j] = (n>>4)*19 + (n&15);
    }
    for (int ck = 0; ck < 4; ck++) {
        __syncthreads();
        for (int i = tid; i < 6144; i += 256) {
            int oc = i/192, k = i - oc*192;
            ws[k*C2WS + oc] = w2[(ocb+oc)*768 + ck*192 + k];
        }
        for (int i = tid; i < 3496; i += 256) {
            int icl = i/437, rem = i - icl*437;
            int row = rem/19, col = rem - row*19;
            int ih = prow0 + row - 2, iw = col - 1;
            padc[i] = (ih>=0 && ih<36 && iw>=0 && iw<16)
                    ? g_h1p[((s*32 + ck*8 + icl)*36 + ih)*16 + iw] : 0.f;
        }
        __syncthreads();
        #pragma unroll 1
        for (int sl = 0; sl < 24; sl++) {
            int icl = sl/3, t8 = (sl - icl*3)*8;
            int kk = icl*24 + t8 + (t&3);
            unsigned A[4];
            A[0] = tf32c(ws[kk*C2WS + m*16 + (t>>2)]);
            A[1] = tf32c(ws[kk*C2WS + m*16 + (t>>2) + 8]);
            A[2] = tf32c(ws[(kk+4)*C2WS + m*16 + (t>>2)]);
            A[3] = tf32c(ws[(kk+4)*C2WS + m*16 + (t>>2) + 8]);
            const float* pb = padc + icl*437 + (t8>>2)*19 + (t&3);  // kh0 = t8/4
            #pragma unroll
            for (int j = 0; j < 9; j++) {
                unsigned B[2];
                B[0] = tf32c(pb[off[j]]);        // kh0,   kw=t&3
                B[1] = tf32c(pb[off[j] + 19]);   // kh0+1, kw=t&3
                mma_tf32(cfr[j], A, B);
            }
        }
    }
    int ocr = ocb + m*16 + (t>>2);
    float b0v = bias[ocr], b8v = bias[ocr+8];
    #pragma unroll
    for (int j = 0; j < 9; j++) {
        int n = 288*blockIdx.z + ng*72 + j*8 + (t&3)*2;
        float* o0 = &g_c2[(s*64 + ocr)*576 + n];
        float* o8 = &g_c2[(s*64 + ocr + 8)*576 + n];
        o0[0] = selu_f(cfr[j][0] + b0v); o0[1] = selu_f(cfr[j][1] + b0v);
        o8[0] = selu_f(cfr[j][2] + b8v); o8[1] = selu_f(cfr[j][3] + b8v);
    }
}

// ===== GN(2ch)+pool(3,4) over conv2 map =====
__global__ void __launch_bounds__(128) k_gnpool2(const float* __restrict__ gg,
        const float* __restrict__ gb) {
    __shared__ float buf[1152];
    __shared__ float red[8];
    int s = blockIdx.x, g = blockIdx.y, tid = threadIdx.x;
    int c0 = 2*g;
    float sm = 0.f, sq = 0.f;
    for (int i = tid; i < 1152; i += 128) {
        float v = g_c2[(s*64 + c0)*576 + i];
        buf[i] = v; sm += v; sq += v*v;
    }
    #pragma unroll
    for (int o = 16; o; o >>= 1) {
        sm += __shfl_xor_sync(0xffffffffu, sm, o);
        sq += __shfl_xor_sync(0xffffffffu, sq, o);
    }
    if ((tid&31) == 0) { red[tid>>5] = sm; red[4 + (tid>>5)] = sq; }
    __syncthreads();
    sm = red[0]+red[1]+red[2]+red[3];
    sq = red[4]+red[5]+red[6]+red[7];
    float mean = sm*(1.f/1152.f);
    float var  = sq*(1.f/1152.f) - mean*mean;
    float inv  = rsqrtf(var + 1e-5f);
    if (tid < 96) {
        int ch = tid/48, rem = tid - ch*48;
        int ph = rem>>2, pw = rem&3;
        float sc = gg[c0+ch]*inv, sh = gb[c0+ch] - mean*sc;
        float mx = -1e30f;
        #pragma unroll
        for (int r = 0; r < 3; r++)
            #pragma unroll
            for (int c = 0; c < 4; c++)
                mx = fmaxf(mx, buf[ch*576 + (3*ph+r)*16 + 4*pw+c]*sc + sh);
        g_h2p[((s*64 + c0 + ch)*12 + ph)*4 + pw] = mx;
    }
}

// ===== conv3: 2 frames/block, 128 oc, grid 512, 512 thr (FFMA2 path) =====
__global__ void __launch_bounds__(512) k_conv3(const float* __restrict__ w,
        const float* __restrict__ bias, const float* __restrict__ gg,
        const float* __restrict__ gb) {
    extern __shared__ float ws[];   // 96*132
    __shared__ float pad[952];
    int tid = threadIdx.x;
    int fr = tid>>8, t2 = tid&255;
    int s = blockIdx.x*2 + fr;
    int quad = t2>>3, wdw = t2&7;
    int ph = wdw>>1, pw = wdw&1;
    float2 acc[3][2][2];
    #pragma unroll
    for (int p = 0; p < 2; p++) {
        float2 b2 = make_float2(bias[quad*4+2*p], bias[quad*4+2*p+1]);
        #pragma unroll
        for (int r = 0; r < 3; r++)
            #pragma unroll
            for (int c = 0; c < 2; c++) acc[r][c][p] = b2;
    }
    for (int ck = 0; ck < 16; ck++) {
        int ic0 = 4*ck;
        __syncthreads();
        for (int i = tid; i < 12288; i += 512) {
            int oc = i/96, r = i - oc*96;
            ws[r*132+oc] = w[oc*1536 + ic0*24 + r];
        }
        for (int i = tid; i < 952; i += 512) {
            int f = i/476, rem = i - f*476;
            int icl = rem/119, rem2 = rem - icl*119;
            int rr = rem2/7, cc = rem2 - rr*7;
            int ih = rr-2, iw = cc-1;
            pad[i] = (ih>=0 && ih<12 && iw>=0 && iw<4)
                   ? g_h2p[(((blockIdx.x*2+f)*64+ic0+icl)*12+ih)*4+iw] : 0.f;
        }
        __syncthreads();
        #pragma unroll 1
        for (int icl = 0; icl < 4; icl++) {
            const float* pb = pad + fr*476 + icl*119;
            #pragma unroll
            for (int kh = 0; kh < 6; kh++) {
                float4 wv[4];
                #pragma unroll
                for (int kw = 0; kw < 4; kw++)
                    wv[kw] = *(const float4*)&ws[(icl*24+kh*4+kw)*132 + 4*quad];
                #pragma unroll
                for (int r = 0; r < 3; r++) {
                    const float* pr = pb + (3*ph+r+kh)*7 + 2*pw;
                    float v[5];
                    #pragma unroll
                    for (int j = 0; j < 5; j++) v[j] = pr[j];
                    #pragma unroll
                    for (int c = 0; c < 2; c++)
                        #pragma unroll
                        for (int kw = 0; kw < 4; kw++) {
                            float2 t = make_float2(v[c+kw], v[c+kw]);
                            acc[r][c][0] = ffma2(t, make_float2(wv[kw].x, wv[kw].y), acc[r][c][0]);
                            acc[r][c][1] = ffma2(t, make_float2(wv[kw].z, wv[kw].w), acc[r][c][1]);
                        }
                }
            }
        }
    }
    float sum = 0.f, sq = 0.f;
    float mx[4] = {-1e30f,-1e30f,-1e30f,-1e30f};
    float mn[4] = { 1e30f, 1e30f, 1e30f, 1e30f};
    #pragma unroll
    for (int r = 0; r < 3; r++)
        #pragma unroll
        for (int c = 0; c < 2; c++) {
            float u0 = selu_f(acc[r][c][0].x), u1 = selu_f(acc[r][c][0].y);
            float u2 = selu_f(acc[r][c][1].x), u3 = selu_f(acc[r][c][1].y);
            sum += u0+u1+u2+u3; sq += u0*u0+u1*u1+u2*u2+u3*u3;
            mx[0]=fmaxf(mx[0],u0); mn[0]=fminf(mn[0],u0);
            mx[1]=fmaxf(mx[1],u1); mn[1]=fminf(mn[1],u1);
            mx[2]=fmaxf(mx[2],u2); mn[2]=fminf(mn[2],u2);
            mx[3]=fmaxf(mx[3],u3); mn[3]=fminf(mn[3],u3);
        }
    #pragma unroll
    for (int o = 4; o; o >>= 1) {
        sum += __shfl_xor_sync(0xffffffffu, sum, o);
        sq  += __shfl_xor_sync(0xffffffffu, sq , o);
    }
    float mean = sum*(1.f/192.f);
    float var  = sq*(1.f/192.f) - mean*mean;
    float inv  = rsqrtf(var+1e-5f);
    #pragma unroll
    for (int p = 0; p < 2; p++)
        #pragma unroll
        for (int e = 0; e < 2; e++) {
            int c = quad*4 + 2*p + e, mi = 2*p + e;
            float scv = gg[c]*inv;
            float shv = gb[c] - mean*scv;
            g_h3p[((s*128+c)*4+ph)*2+pw] = scv>0.f ? mx[mi]*scv+shv : mn[mi]*scv+shv;
        }
}

// ===== fc: 8 rows/block, 128 blocks =====
__global__ void __launch_bounds__(256) k_fc(const float* __restrict__ w,
        const float* __restrict__ bias) {
    __shared__ float xs[8*65];
    __shared__ float wt[64*129];
    __shared__ float sred[8][4];
    int r0 = blockIdx.x*8, tid = threadIdx.x;
    int c = tid&127, rg = tid>>7, wrp = tid>>5, ln = tid&31;
    float acc[4];
    float b0 = bias[c];
    #pragma unroll
    for (int rr = 0; rr < 4; rr++) acc[rr] = b0;
    for (int k0 = 0; k0 < 1024; k0 += 64) {
        __syncthreads();
        for (int i = tid; i < 512; i += 256) {
            int r = i>>6, kk = i&63;
            xs[r*65+kk] = g_h3p[(r0+r)*1024 + k0 + kk];
        }
        for (int i = tid; i < 8192; i += 256) {
            int j = i>>6, kk = i&63;
            wt[kk*129+j] = w[j*1024 + k0 + kk];
        }
        __syncthreads();
        for (int kk = 0; kk < 64; kk++) {
            float wv = wt[kk*129+c];
            #pragma unroll
            for (int rr = 0; rr < 4; rr++) acc[rr] += xs[(rg*4+rr)*65+kk]*wv;
        }
    }
    float v[4];
    #pragma unroll
    for (int rr = 0; rr < 4; rr++) v[rr] = selu_f(acc[rr]);
    #pragma unroll
    for (int rr = 0; rr < 4; rr++) {
        float ss = v[rr]*v[rr];
        #pragma unroll
        for (int o = 16; o; o >>= 1) ss += __shfl_xor_sync(0xffffffffu, ss, o);
        if (ln == 0) sred[wrp][rr] = ss;
    }
    __syncthreads();
    #pragma unroll
    for (int rr = 0; rr < 4; rr++) {
        float t = sred[rg*4+0][rr] + sred[rg*4+1][rr] + sred[rg*4+2][rr] + sred[rg*4+3][rr];
        float n = fmaxf(sqrtf(t), 1e-12f);
        g_e[(r0+rg*4+rr)*128 + c] = v[rr]/n;
    }
}

// ===== qkv: 8 rows/block, 128 blocks =====
__global__ void __launch_bounds__(256) k_qkv(const float* __restrict__ wq,
        const float* __restrict__ bq, const float* __restrict__ wk,
        const float* __restrict__ bk, const float* __restrict__ wv,
        const float* __restrict__ bv) {
    __shared__ float es[8*132];
    __shared__ float wt[64*129];
    int r0 = blockIdx.x*8, tid = threadIdx.x;
    int c = tid&127, rg = tid>>7;
    for (int i = tid; i < 1024; i += 256) {
        int r = i>>7, d = i&127;
        es[r*132+d] = g_e[(r0+r)*128 + d];
    }
    const float* W[3] = {wq, wk, wv};
    const float* B[3] = {bq, bk, bv};
    float* O[3] = {g_q, g_k, g_v};
    for (int m = 0; m < 3; m++) {
        float acc[4];
        float b0 = B[m][c];
        #pragma unroll
        for (int rr = 0; rr < 4; rr++) acc[rr] = b0;
        for (int k0 = 0; k0 < 128; k0 += 64) {
            __syncthreads();
            for (int i = tid; i < 8192; i += 256) {
                int j = i>>6, kk = i&63;
                wt[kk*129+j] = W[m][j*128 + k0 + kk];
            }
            __syncthreads();
            for (int kk = 0; kk < 64; kk++) {
                float wvv = wt[kk*129+c];
                #pragma unroll
                for (int rr = 0; rr < 4; rr++) acc[rr] += es[(rg*4+rr)*132 + k0 + kk]*wvv;
            }
        }
        #pragma unroll
        for (int rr = 0; rr < 4; rr++) {
            int sr = r0 + rg*4 + rr;
            float u = selu_f(acc[rr]);
            if (m == 1) {
                float f = expf((float)(c & ~1) * (-9.210340371976184f/128.f));
                float ang = (float)sr * f;
                u += (c & 1) ? cosf(ang) : sinf(ang);
            }
            O[m][sr*128 + c] = u;
        }
    }
}

// ===== attn: 8 rows/block, 128 blocks =====
__global__ void __launch_bounds__(256) k_attn() {
    __shared__ __align__(16) float q8[8*132];
    __shared__ float p[8*1024];
    __shared__ float rinv[8];
    __shared__ float part[8*128];
    int r0 = blockIdx.x*8, tid = threadIdx.x;
    for (int i = tid; i < 1024; i += 256) {
        int r = i>>7, d = i&127;
        q8[r*132+d] = g_q[(r0+r)*128 + d];
    }
    __syncthreads();
    const float scale = 0.08838834764831845f;
    for (int t = tid; t < 1024; t += 256) {
        float a[8] = {0,0,0,0,0,0,0,0};
        const float4* kr = (const float4*)(g_k + t*128);
        #pragma unroll 8
        for (int d4 = 0; d4 < 32; d4++) {
            float4 kv = kr[d4];
            #pragma unroll
            for (int r = 0; r < 8; r++) {
                float4 qv = *(const float4*)&q8[r*132 + d4*4];
                a[r] += qv.x*kv.x + qv.y*kv.y + qv.z*kv.z + qv.w*kv.w;
            }
        }
        #pragma unroll
        for (int r = 0; r < 8; r++) p[r*1024+t] = a[r]*scale;
    }
    __syncthreads();
    int wrp = tid>>5, ln = tid&31;
    {
        int r = wrp;
        float mxv = -1e30f;
        for (int t = ln; t < 1024; t += 32) mxv = fmaxf(mxv, p[r*1024+t]);
        #pragma unroll
        for (int o = 16; o; o >>= 1) mxv = fmaxf(mxv, __shfl_xor_sync(0xffffffffu, mxv, o));
        float sm = 0.f;
        for (int t = ln; t < 1024; t += 32) {
            float e = expf(p[r*1024+t] - mxv);
            p[r*1024+t] = e;
            sm += e;
        }
        #pragma unroll
        for (int o = 16; o; o >>= 1) sm += __shfl_xor_sync(0xffffffffu, sm, o);
        if (ln == 0) rinv[r] = 1.f/sm;
    }
    __syncthreads();
    int c = tid&127, hf = tid>>7;
    float a[8] = {0,0,0,0,0,0,0,0};
    for (int t = hf*512; t < hf*512+512; t++) {
        float vv = g_v[t*128 + c];
        #pragma unroll
        for (int r = 0; r < 8; r++) a[r] += p[r*1024+t]*vv;
    }
    if (hf) {
        #pragma unroll
        for (int r = 0; r < 8; r++) part[r*128+c] = a[r];
    }
    __syncthreads();
    if (!hf) {
        #pragma unroll
        for (int r = 0; r < 8; r++)
            g_ao[(r0+r)*128+c] = (a[r] + part[r*128+c])*rinv[r];
    }
}

__global__ void __launch_bounds__(256) k_cs1() {
    __shared__ float red[128];
    int s0 = blockIdx.x*16, tid = threadIdx.x;
    int c = tid&127, sy = tid>>7;
    float ss = 0.f;
    for (int s = sy; s < 16; s += 2) { float v = g_ao[(s0+s)*128+c]; ss += v*v; }
    if (sy) red[c] = ss;
    __syncthreads();
    if (!sy) atomicAdd(&g_css[c], ss + red[c]);
}

__global__ void __launch_bounds__(256) k_cs2() {
    __shared__ float red[128];
    int s0 = blockIdx.x*16, tid = threadIdx.x;
    int c = tid&127, sy = tid>>7;
    float inv1 = 1.f/fmaxf(sqrtf(g_css[c]), 1e-12f);
    float ss = 0.f;
    for (int s = sy; s < 16; s += 2) {
        float v = g_ao[(s0+s)*128+c]*inv1 + g_e[(s0+s)*128+c];
        g_o2[(s0+s)*128+c] = v;
        ss += v*v;
    }
    if (sy) red[c] = ss;
    __syncthreads();
    if (!sy) atomicAdd(&g_css2[c], ss + red[c]);
}

__global__ void __launch_bounds__(256) k_cs3() {
    int i = blockIdx.x*256 + threadIdx.x;
    int c = i&127;
    float inv2 = 1.f/fmaxf(sqrtf(g_css2[c]), 1e-12f);
    g_ea[i] = g_o2[i]*inv2;
}

__global__ void k_rowsq() {
    int s = blockIdx.x*128 + threadIdx.x;
    const float4* r = (const float4*)(g_ea + s*128);
    float ss = 0.f;
    #pragma unroll
    for (int i = 0; i < 32; i++) {
        float4 v = r[i];
        ss += v.x*v.x + v.y*v.y + v.z*v.z + v.w*v.w;
    }
    g_sq[s] = ss;
}

__global__ void k_gram(float* __restrict__ dout) {
    __shared__ float ea_i[32][129];
    __shared__ float ea_j[32][129];
    __shared__ float sqi[32], sqj[32];
    __shared__ float rmax[8];
    int i0 = blockIdx.y*32, j0 = blockIdx.x*32;
    int tid = threadIdx.x;
    for (int idx = tid; idx < 4096; idx += 256) {
        int r = idx>>7, d = idx&127;
        ea_i[r][d] = g_ea[(i0+r)*128+d];
        ea_j[r][d] = g_ea[(j0+r)*128+d];
    }
    if (tid < 32) { sqi[tid] = g_sq[i0+tid]; sqj[tid] = g_sq[j0+tid]; }
    __syncthreads();
    int tx = tid&15, ty = tid>>4;
    int r0 = 2*ty, c0 = 2*tx;
    float d00 = 0.f, d01 = 0.f, d10 = 0.f, d11 = 0.f;
    #pragma unroll 4
    for (int d = 0; d < 128; d++) {
        float a0 = ea_i[r0][d], a1 = ea_i[r0+1][d];
        float b0 = ea_j[c0][d], b1 = ea_j[c0+1][d];
        d00 += a0*b0; d01 += a0*b1; d10 += a1*b0; d11 += a1*b1;
    }
    float lm = 0.f;
    float dots[4] = {d00, d01, d10, d11};
    #pragma unroll
    for (int u = 0; u < 4; u++) {
        int r = r0 + (u>>1), c = c0 + (u&1);
        float d2 = fmaxf(sqi[r] + sqj[c] - 2.f*dots[u], 0.f);
        float dd = sqrtf(d2 + 1e-12f);
        dout[(i0+r)*1024 + j0 + c] = dd;
        lm = fmaxf(lm, dd);
    }
    #pragma unroll
    for (int o = 16; o; o >>= 1) lm = fmaxf(lm, __shfl_xor_sync(0xffffffffu, lm, o));
    if ((tid&31) == 0) rmax[tid>>5] = lm;
    __syncthreads();
    if (tid == 0) {
        float m = 0.f;
        for (int i = 0; i < 8; i++) m = fmaxf(m, rmax[i]);
        atomicMax(&g_dmax, __float_as_uint(m));
    }
}

__global__ void k_final(float* __restrict__ dout) {
    float inv = 1.f/__uint_as_float(g_dmax);
    int i = blockIdx.x*256 + threadIdx.x;
    dout[i] = 1.f - dout[i]*inv;
}

extern "C" void kernel_launch(void* const* d_in, const int* in_sizes, int n_in,
                              void* d_out, int out_size) {
    const float* x   = (const float*)d_in[0];
    const float* c1w = (const float*)d_in[1];
    const float* c1b = (const float*)d_in[2];
    const float* g1g = (const float*)d_in[3];
    const float* g1b = (const float*)d_in[4];
    const float* c2w = (const float*)d_in[5];
    const float* c2b = (const float*)d_in[6];
    const float* g2g = (const float*)d_in[7];
    const float* g2b = (const float*)d_in[8];
    const float* c3w = (const float*)d_in[9];
    const float* c3b = (const float*)d_in[10];
    const float* g3g = (const float*)d_in[11];
    const float* g3b = (const float*)d_in[12];
    const float* fcw = (const float*)d_in[13];
    const float* fcb = (const float*)d_in[14];
    const float* wq  = (const float*)d_in[15];
    const float* bq  = (const float*)d_in[16];
    const float* wk  = (const float*)d_in[17];
    const float* bk  = (const float*)d_in[18];
    const float* wv  = (const float*)d_in[19];
    const float* bv  = (const float*)d_in[20];
    float* out = (float*)d_out;

    cudaFuncSetAttribute(k_conv3, cudaFuncAttributeMaxDynamicSharedMemorySize, 96*132*4);

    k_zero<<<1, 256>>>();
    k_conv1<<<1024, 256>>>(x, c1w, c1b, g1g, g1b);
    k_conv2mma<<<dim3(1024,2,2), 256>>>(c2w, c2b);
    k_gnpool2<<<dim3(1024,32), 128>>>(g2g, g2b);
    k_conv3<<<512, 512, 96*132*4>>>(c3w, c3b, g3g, g3b);
    k_fc  <<<128, 256>>>(fcw, fcb);
    k_qkv <<<128, 256>>>(wq, bq, wk, bk, wv, bv);
    k_attn<<<128, 256>>>();
    k_cs1 <<<64, 256>>>();
    k_cs2 <<<64, 256>>>();
    k_cs3 <<<512, 256>>>();
    k_rowsq<<<8, 128>>>();
    k_gram<<<dim3(32,32), 256>>>(out);
    k_final<<<4096, 256>>>(out);
}